// round 10
// baseline (speedup 1.0000x reference)
#include <cuda_runtime.h>
#include <cuda_fp16.h>
#include <cuda_bf16.h>

#define NN 50000
#define NE 800000
#define IND 128
#define HID 64

// ---------------- scratch (device globals; no runtime allocation) ----------
__device__ int    g_deg_in[NN];
__device__ int    g_deg_out[NN];
__device__ int    g_row_beg[NN];
__device__ int    g_cursor[NN];
__device__ int    g_total;
__device__ int    g_esrc[NE];
__device__ float  g_din[NN];
__device__ float  g_dout[NN];
__device__ float  g_bufB[NN * IND];   // gcn: spmm128 out (128-dim)
__device__ float  g_bufA[NN * HID];   // gcn: dummy C for NOC gemm
__device__ float  g_h [NN * HID];
__device__ float  g_f1[NN * HID];
__device__ float  g_s [NN * HID];
// fp16 gather tables
__device__ __half g_in16[NN * IND];
__device__ __half g_h16 [NN * HID];
__device__ __half g_f116[NN * HID];
__device__ __half g_a16 [NN * HID];

// ---------------- packed fp32x2 FMA (Blackwell FFMA2) ----------------------
__device__ __forceinline__ float2 f2fma(float2 a, float2 b, float2 c) {
    unsigned long long ua = *reinterpret_cast<unsigned long long*>(&a);
    unsigned long long ub = *reinterpret_cast<unsigned long long*>(&b);
    unsigned long long uc = *reinterpret_cast<unsigned long long*>(&c);
    unsigned long long ud;
    asm("fma.rn.f32x2 %0, %1, %2, %3;" : "=l"(ud) : "l"(ua), "l"(ub), "l"(uc));
    return *reinterpret_cast<float2*>(&ud);
}

// ---------------- graph prep ----------------
__global__ void k_zero_deg() {
    int i = blockIdx.x * blockDim.x + threadIdx.x;
    if (i < NN) { g_deg_in[i] = 0; g_deg_out[i] = 0; }
    if (i == 0) g_total = 0;
}

__global__ void k_deg(const int* __restrict__ src, const int* __restrict__ dst) {
    int e = blockIdx.x * blockDim.x + threadIdx.x;
    if (e < NE) {
        atomicAdd(&g_deg_in[dst[e]], 1);
        atomicAdd(&g_deg_out[src[e]], 1);
    }
}

__global__ void k_offsets() {
    int i = blockIdx.x * blockDim.x + threadIdx.x;
    if (i < NN) {
        int d = g_deg_in[i];
        int pos = atomicAdd(&g_total, d);
        g_row_beg[i] = pos;
        g_cursor[i]  = pos;
        g_din[i]  = rsqrtf((float)max(d, 1));
        g_dout[i] = rsqrtf((float)max(g_deg_out[i], 1));
    }
}

__global__ void k_scatter(const int* __restrict__ src, const int* __restrict__ dst) {
    int e = blockIdx.x * blockDim.x + threadIdx.x;
    if (e < NE) {
        int v = dst[e];
        int pos = atomicAdd(&g_cursor[v], 1);
        g_esrc[pos] = src[e];
    }
}

// ---------------- fp32 -> fp16 convert (for in_feat) -----------------------
__global__ void k_cvt(const float4* __restrict__ x, uint2* __restrict__ y, int n4) {
    int i = blockIdx.x * blockDim.x + threadIdx.x;
    if (i < n4) {
        float4 t = x[i];
        __half2 lo = __floats2half2_rn(t.x, t.y);
        __half2 hi = __floats2half2_rn(t.z, t.w);
        uint2 o;
        o.x = *reinterpret_cast<unsigned*>(&lo);
        o.y = *reinterpret_cast<unsigned*>(&hi);
        y[i] = o;
    }
}

// ---------------- spmm, fp16 gather, fp32 accumulate (warp per node) -------
__global__ void k_spmm64h(const __half2* __restrict__ x16, const float* __restrict__ gsc,
                          const float* __restrict__ base, float* __restrict__ y,
                          __half2* __restrict__ y16, int mode) {
    int w = (blockIdx.x * blockDim.x + threadIdx.x) >> 5;
    int lane = threadIdx.x & 31;
    if (w >= NN) return;
    int beg = g_row_beg[w];
    int end = beg + g_deg_in[w];
    float2 acc = make_float2(0.f, 0.f);
    #pragma unroll 4
    for (int j = beg; j < end; j++) {
        int u = g_esrc[j];
        float s = gsc[u];
        float2 t = __half22float2(x16[u * 32 + lane]);
        acc.x += t.x * s;
        acc.y += t.y * s;
    }
    float sd = g_din[w];
    float2 r;
    if (mode) {
        float2 b = *reinterpret_cast<const float2*>(base + w * 64 + lane * 2);
        r.x = b.x - acc.x * sd;
        r.y = b.y - acc.y * sd;
    } else {
        r.x = acc.x * sd;
        r.y = acc.y * sd;
    }
    *reinterpret_cast<float2*>(y + w * 64 + lane * 2) = r;
    if (y16) y16[w * 32 + lane] = __floats2half2_rn(r.x, r.y);
}

__global__ void k_spmm128h(const uint2* __restrict__ x16, const float* __restrict__ gsc,
                           float* __restrict__ y) {
    int w = (blockIdx.x * blockDim.x + threadIdx.x) >> 5;
    int lane = threadIdx.x & 31;
    if (w >= NN) return;
    int beg = g_row_beg[w];
    int end = beg + g_deg_in[w];
    float4 acc = make_float4(0.f, 0.f, 0.f, 0.f);
    #pragma unroll 4
    for (int j = beg; j < end; j++) {
        int u = g_esrc[j];
        float s = gsc[u];
        uint2 p = x16[u * 32 + lane];
        float2 lo = __half22float2(*reinterpret_cast<__half2*>(&p.x));
        float2 hi = __half22float2(*reinterpret_cast<__half2*>(&p.y));
        acc.x += lo.x * s; acc.y += lo.y * s;
        acc.z += hi.x * s; acc.w += hi.y * s;
    }
    float sd = g_din[w];
    acc.x *= sd; acc.y *= sd; acc.z *= sd; acc.w *= sd;
    *reinterpret_cast<float4*>(y + w * 128 + lane * 4) = acc;
}

// ---------------- fp32x2 GEMM inner (templated smem strides) ---------------
#define GF_BIAS 2
#define GF_RELU 4
#define GF_NOC  8
#define KT 32

template<int SA, int SB>
__device__ __forceinline__ void gemm_inner(const float (*As)[SA], int aofs,
                                           const float (*Bs)[SB], int bofs,
                                           float2 (&acc)[4][2], int tx, int ty) {
    #pragma unroll
    for (int kk = 0; kk < KT; kk += 4) {
        float4 a4[4];
        #pragma unroll
        for (int i = 0; i < 4; i++)
            a4[i] = *reinterpret_cast<const float4*>(&As[ty * 4 + i][aofs + kk]);
        #pragma unroll
        for (int q = 0; q < 4; q++) {
            float4 bv = *reinterpret_cast<const float4*>(&Bs[bofs + kk + q][tx * 4]);
            float2 b01 = make_float2(bv.x, bv.y);
            float2 b23 = make_float2(bv.z, bv.w);
            #pragma unroll
            for (int i = 0; i < 4; i++) {
                float a = (q == 0) ? a4[i].x : (q == 1) ? a4[i].y
                        : (q == 2) ? a4[i].z : a4[i].w;
                float2 aa = make_float2(a, a);
                acc[i][0] = f2fma(aa, b01, acc[i][0]);
                acc[i][1] = f2fma(aa, b23, acc[i][1]);
            }
        }
    }
}

// ---------------- generic tiled GEMM: C = epi(A[M,K] @ B[K,N]) -------------
__global__ void __launch_bounds__(256)
k_gemm(const float* __restrict__ A, const float* __restrict__ B,
       const float* __restrict__ bias, float* __restrict__ C,
       __half* __restrict__ Ch, int M, int K, int N, int flags) {
    __shared__ float As2[64][KT + 4];
    __shared__ float Bs[KT][68];
    int tid = threadIdx.x;
    int tx = tid & 15;
    int ty = tid >> 4;
    int rowBase = blockIdx.y * 64;
    int colBase = blockIdx.x * 64;
    float2 acc[4][2] = {};
    for (int k0 = 0; k0 < K; k0 += KT) {
        #pragma unroll 2
        for (int l = tid; l < 512; l += 256) {
            int r = l >> 3, ks = (l & 7) << 2;
            int row = rowBase + r;
            float4 v = make_float4(0.f, 0.f, 0.f, 0.f);
            if (row < M) v = *reinterpret_cast<const float4*>(A + (size_t)row * K + k0 + ks);
            *reinterpret_cast<float4*>(&As2[r][ks]) = v;
        }
        #pragma unroll 2
        for (int l = tid; l < 512; l += 256) {
            int kk = l >> 4, c = (l & 15) << 2;
            *reinterpret_cast<float4*>(&Bs[kk][c]) =
                *reinterpret_cast<const float4*>(B + (size_t)(k0 + kk) * N + colBase + c);
        }
        __syncthreads();
        gemm_inner<KT + 4, 68>(As2, 0, Bs, 0, acc, tx, ty);
        __syncthreads();
    }
    int col0 = colBase + tx * 4;
    float4 bb = make_float4(0.f, 0.f, 0.f, 0.f);
    if (flags & GF_BIAS) bb = *reinterpret_cast<const float4*>(bias + col0);
    #pragma unroll
    for (int i = 0; i < 4; i++) {
        int row = rowBase + ty * 4 + i;
        if (row >= M) continue;
        float4 v = make_float4(acc[i][0].x + bb.x, acc[i][0].y + bb.y,
                               acc[i][1].x + bb.z, acc[i][1].y + bb.w);
        if (flags & GF_RELU) {
            v.x = fmaxf(v.x, 0.f); v.y = fmaxf(v.y, 0.f);
            v.z = fmaxf(v.z, 0.f); v.w = fmaxf(v.w, 0.f);
        }
        if (!(flags & GF_NOC))
            *reinterpret_cast<float4*>(C + (size_t)row * N + col0) = v;
        if (Ch) {
            __half2 lo = __floats2half2_rn(v.x, v.y);
            __half2 hi = __floats2half2_rn(v.z, v.w);
            uint2 o;
            o.x = *reinterpret_cast<unsigned*>(&lo);
            o.y = *reinterpret_cast<unsigned*>(&hi);
            *reinterpret_cast<uint2*>(Ch + (size_t)row * N + col0) = o;
        }
    }
}

// ---------------- fused head: gathers f2 = L f1 in-block, then
//   out = relu(h@Wa + f1@Wb + f2@Wc + b3) @ W4 + b4,  Wa/Wb/Wc from W3 -----
__global__ void __launch_bounds__(256)
k_head_fused(const float* __restrict__ W3, const float* __restrict__ b3,
             const float* __restrict__ W4, const float* __restrict__ b4,
             float* __restrict__ out) {
    __shared__ float As2[64][KT + 4];
    __shared__ float Bs[KT][68];
    __shared__ float Fs[64][68];
    int tid = threadIdx.x;
    int tx = tid & 15;
    int ty = tid >> 4;
    int warp = tid >> 5;
    int lane = tid & 31;
    int rowBase = blockIdx.x * 64;

    // phase 1: gather f2 rows for this tile: f2[v] = f1[v] - din[v]*sum din[u]*f116[u]
    #pragma unroll 1
    for (int i = 0; i < 8; i++) {
        int row = warp * 8 + i;
        int v = rowBase + row;
        float2 r = make_float2(0.f, 0.f);
        if (v < NN) {
            int beg = g_row_beg[v];
            int end = beg + g_deg_in[v];
            float2 acc = make_float2(0.f, 0.f);
            #pragma unroll 4
            for (int j = beg; j < end; j++) {
                int u = g_esrc[j];
                float s = g_din[u];
                float2 t = __half22float2(*reinterpret_cast<const __half2*>(g_f116 + u * 64 + lane * 2));
                acc.x += t.x * s;
                acc.y += t.y * s;
            }
            float sd = g_din[v];
            float2 b = *reinterpret_cast<const float2*>(g_f1 + (size_t)v * 64 + lane * 2);
            r.x = b.x - acc.x * sd;
            r.y = b.y - acc.y * sd;
        }
        Fs[row][lane * 2]     = r.x;
        Fs[row][lane * 2 + 1] = r.y;
    }
    __syncthreads();

    // phase 2: 3-source GEMM accumulation
    float2 acc[4][2] = {};
    #pragma unroll
    for (int s3 = 0; s3 < 3; s3++) {
        const float* A = (s3 == 0) ? g_h : g_f1;
        #pragma unroll
        for (int k0 = 0; k0 < 64; k0 += KT) {
            // B tile: combine W3 blocks into theta-weights
            #pragma unroll 2
            for (int l = tid; l < 512; l += 256) {
                int kk = l >> 4, c = (l & 15) << 2;
                int k = k0 + kk;
                float4 w0 = *reinterpret_cast<const float4*>(W3 + (size_t)k * 64 + c);
                float4 v;
                if (s3 == 0) {
                    v = make_float4(3.f * w0.x, 3.f * w0.y, 3.f * w0.z, 3.f * w0.w);
                } else if (s3 == 1) {
                    float4 w1 = *reinterpret_cast<const float4*>(W3 + (size_t)(64 + k) * 64 + c);
                    float4 w3v = *reinterpret_cast<const float4*>(W3 + (size_t)(192 + k) * 64 + c);
                    v = make_float4(-3.f * w0.x + 3.f * w1.x + w3v.x,
                                    -3.f * w0.y + 3.f * w1.y + w3v.y,
                                    -3.f * w0.z + 3.f * w1.z + w3v.z,
                                    -3.f * w0.w + 3.f * w1.w + w3v.w);
                } else {
                    float4 w1 = *reinterpret_cast<const float4*>(W3 + (size_t)(64 + k) * 64 + c);
                    float4 w2 = *reinterpret_cast<const float4*>(W3 + (size_t)(128 + k) * 64 + c);
                    float4 w4v = *reinterpret_cast<const float4*>(W3 + (size_t)(256 + k) * 64 + c);
                    v = make_float4(0.75f * w0.x - 1.5f * w1.x + 0.75f * w2.x + w4v.x,
                                    0.75f * w0.y - 1.5f * w1.y + 0.75f * w2.y + w4v.y,
                                    0.75f * w0.z - 1.5f * w1.z + 0.75f * w2.z + w4v.z,
                                    0.75f * w0.w - 1.5f * w1.w + 0.75f * w2.w + w4v.w);
                }
                *reinterpret_cast<float4*>(&Bs[kk][c]) = v;
            }
            if (s3 < 2) {
                #pragma unroll 2
                for (int l = tid; l < 512; l += 256) {
                    int r = l >> 3, ks = (l & 7) << 2;
                    int row = rowBase + r;
                    float4 v = make_float4(0.f, 0.f, 0.f, 0.f);
                    if (row < NN) v = *reinterpret_cast<const float4*>(A + (size_t)row * 64 + k0 + ks);
                    *reinterpret_cast<float4*>(&As2[r][ks]) = v;
                }
            }
            __syncthreads();
            if (s3 == 2) gemm_inner<68, 68>(Fs, k0, Bs, 0, acc, tx, ty);
            else         gemm_inner<KT + 4, 68>(As2, 0, Bs, 0, acc, tx, ty);
            __syncthreads();
        }
    }

    // epilogue: z = relu(acc + b3), then 64->2 contraction with W4
    int col0 = tx * 4;
    float4 bb = *reinterpret_cast<const float4*>(b3 + col0);
    float w40[4], w41[4];
    #pragma unroll
    for (int jj = 0; jj < 4; jj++) {
        w40[jj] = W4[(col0 + jj) * 2];
        w41[jj] = W4[(col0 + jj) * 2 + 1];
    }
    float o0 = b4[0], o1 = b4[1];
    #pragma unroll
    for (int i = 0; i < 4; i++) {
        float z0 = fmaxf(acc[i][0].x + bb.x, 0.f);
        float z1 = fmaxf(acc[i][0].y + bb.y, 0.f);
        float z2 = fmaxf(acc[i][1].x + bb.z, 0.f);
        float z3 = fmaxf(acc[i][1].y + bb.w, 0.f);
        float p0 = z0 * w40[0] + z1 * w40[1] + z2 * w40[2] + z3 * w40[3];
        float p1 = z0 * w41[0] + z1 * w41[1] + z2 * w41[2] + z3 * w41[3];
        #pragma unroll
        for (int off = 8; off >= 1; off >>= 1) {
            p0 += __shfl_down_sync(0xffffffffu, p0, off, 16);
            p1 += __shfl_down_sync(0xffffffffu, p1, off, 16);
        }
        int row = rowBase + ty * 4 + i;
        if (tx == 0 && row < NN) {
            out[row * 2]     = p0 + o0;
            out[row * 2 + 1] = p1 + o1;
        }
    }
}

// ---------------- fused GCN tail: gather din*sum(dout*a16) in-block,
//   then emb = As @ Wg2 + bg2   (N = 128 via two 64-col passes) -------------
__global__ void __launch_bounds__(256)
k_gcn2_fused(const float* __restrict__ Wg2, const float* __restrict__ bg2,
             float* __restrict__ emb) {
    __shared__ float As[64][68];
    __shared__ float Bs[64][68];
    int tid = threadIdx.x;
    int tx = tid & 15;
    int ty = tid >> 4;
    int warp = tid >> 5;
    int lane = tid & 31;
    int rowBase = blockIdx.x * 64;

    // phase 1: gather
    #pragma unroll 1
    for (int i = 0; i < 8; i++) {
        int row = warp * 8 + i;
        int v = rowBase + row;
        float2 r = make_float2(0.f, 0.f);
        if (v < NN) {
            int beg = g_row_beg[v];
            int end = beg + g_deg_in[v];
            float2 acc = make_float2(0.f, 0.f);
            #pragma unroll 4
            for (int j = beg; j < end; j++) {
                int u = g_esrc[j];
                float s = g_dout[u];
                float2 t = __half22float2(*reinterpret_cast<const __half2*>(g_a16 + u * 64 + lane * 2));
                acc.x += t.x * s;
                acc.y += t.y * s;
            }
            float sd = g_din[v];
            r.x = acc.x * sd;
            r.y = acc.y * sd;
        }
        As[row][lane * 2]     = r.x;
        As[row][lane * 2 + 1] = r.y;
    }
    __syncthreads();

    // phase 2: two 64-col GEMM passes over Wg2 [64,128]
    #pragma unroll 1
    for (int cb = 0; cb < 128; cb += 64) {
        #pragma unroll 4
        for (int l = tid; l < 1024; l += 256) {
            int kk = l >> 4, c = (l & 15) << 2;
            *reinterpret_cast<float4*>(&Bs[kk][c]) =
                *reinterpret_cast<const float4*>(Wg2 + (size_t)kk * 128 + cb + c);
        }
        __syncthreads();
        float2 acc[4][2] = {};
        gemm_inner<68, 68>(As, 0,  Bs, 0,  acc, tx, ty);
        gemm_inner<68, 68>(As, 32, Bs, 32, acc, tx, ty);
        int col0 = cb + tx * 4;
        float4 bb = *reinterpret_cast<const float4*>(bg2 + col0);
        #pragma unroll
        for (int i = 0; i < 4; i++) {
            int row = rowBase + ty * 4 + i;
            if (row < NN) {
                float4 v = make_float4(acc[i][0].x + bb.x, acc[i][0].y + bb.y,
                                       acc[i][1].x + bb.z, acc[i][1].y + bb.w);
                *reinterpret_cast<float4*>(emb + (size_t)row * 128 + col0) = v;
            }
        }
        __syncthreads();
    }
}

// ---------------- launch (two forked streams inside capture) ---------------
extern "C" void kernel_launch(void* const* d_in, const int* in_sizes, int n_in,
                              void* d_out, int out_size) {
    const float* in_feat = (const float*)d_in[0];
    const int*   src     = (const int*)d_in[1];
    const int*   dst     = (const int*)d_in[2];
    const float* W1 = (const float*)d_in[3];
    const float* b1 = (const float*)d_in[4];
    const float* W2 = (const float*)d_in[5];
    const float* b2 = (const float*)d_in[6];
    const float* W3 = (const float*)d_in[7];
    const float* b3 = (const float*)d_in[8];
    const float* W4 = (const float*)d_in[9];
    const float* b4 = (const float*)d_in[10];
    const float* Wg1 = (const float*)d_in[11];
    const float* bg1 = (const float*)d_in[12];
    const float* Wg2 = (const float*)d_in[13];
    const float* bg2 = (const float*)d_in[14];

    float* out = (float*)d_out;          // [NN,2]
    float* emb = out + NN * 2;           // [NN,128]

    float  *p_h, *p_f1, *p_s, *p_bufA, *p_bufB, *p_din, *p_dout;
    __half *p_in16, *p_h16, *p_f116, *p_a16;
    cudaGetSymbolAddress((void**)&p_h,    g_h);
    cudaGetSymbolAddress((void**)&p_f1,   g_f1);
    cudaGetSymbolAddress((void**)&p_s,    g_s);
    cudaGetSymbolAddress((void**)&p_bufA, g_bufA);
    cudaGetSymbolAddress((void**)&p_bufB, g_bufB);
    cudaGetSymbolAddress((void**)&p_din,  g_din);
    cudaGetSymbolAddress((void**)&p_dout, g_dout);
    cudaGetSymbolAddress((void**)&p_in16, g_in16);
    cudaGetSymbolAddress((void**)&p_h16,  g_h16);
    cudaGetSymbolAddress((void**)&p_f116, g_f116);
    cudaGetSymbolAddress((void**)&p_a16,  g_a16);

    // streams/events created once on the uncaptured correctness call; reused
    // during capture (creation during capture is illegal). Same work per call.
    static cudaStream_t s1 = nullptr, s2 = nullptr;
    static cudaEvent_t evRoot, evGraph, evS1, evS2;
    if (!s1) {
        cudaStreamCreateWithFlags(&s1, cudaStreamNonBlocking);
        cudaStreamCreateWithFlags(&s2, cudaStreamNonBlocking);
        cudaEventCreateWithFlags(&evRoot,  cudaEventDisableTiming);
        cudaEventCreateWithFlags(&evGraph, cudaEventDisableTiming);
        cudaEventCreateWithFlags(&evS1,    cudaEventDisableTiming);
        cudaEventCreateWithFlags(&evS2,    cudaEventDisableTiming);
    }

    const int TB = 256;
    int nBlkN = (NN + TB - 1) / TB;
    int nBlkE = (NE + TB - 1) / TB;
    int spmmBlocks = (NN * 32 + TB - 1) / TB;
    dim3 g64(1, (NN + 63) / 64);
    int tileBlocks = (NN + 63) / 64;

    // ---- fork ----
    cudaEventRecord(evRoot, 0);
    cudaStreamWaitEvent(s1, evRoot, 0);
    cudaStreamWaitEvent(s2, evRoot, 0);

    // Submission order puts k_gemm (K=64) at kernel slot #4 — the slot ncu's
    // "-s 5 -c 1" capture lands on — so next round profiles a GEMM.
    k_zero_deg<<<nBlkN, TB>>>();                                           // 1
    k_deg<<<nBlkE, TB>>>(src, dst);                                        // 2
    k_gemm<<<g64, 256, 0, s1>>>(in_feat, W1, b1, p_s, nullptr,
                                NN, 128, 64, GF_BIAS | GF_RELU);           // 3
    k_gemm<<<g64, 256, 0, s1>>>(p_s, W2, b2, p_h, p_h16,
                                NN, 64, 64, GF_BIAS | GF_RELU);            // 4 (profiled)
    k_cvt<<<(NN * 32 + TB - 1) / TB, TB, 0, s2>>>((const float4*)in_feat,
                                                  (uint2*)p_in16, NN * 32); // 5
    k_offsets<<<nBlkN, TB>>>();                                            // 6
    k_scatter<<<nBlkE, TB>>>(src, dst);                                    // 7
    cudaEventRecord(evGraph, 0);

    // ---- s1: band branch (needs graph) ----
    cudaStreamWaitEvent(s1, evGraph, 0);
    k_spmm64h<<<spmmBlocks, TB, 0, s1>>>((const __half2*)p_h16, p_din, p_h,
                                         p_f1, (__half2*)p_f116, 1);       // 8
    k_head_fused<<<tileBlocks, 256, 0, s1>>>(W3, b3, W4, b4, out);         // 9
    cudaEventRecord(evS1, s1);

    // ---- s2: GCN branch (needs graph + in16) ----
    cudaStreamWaitEvent(s2, evGraph, 0);
    k_spmm128h<<<spmmBlocks, TB, 0, s2>>>((const uint2*)p_in16, p_dout, p_bufB); // 10
    k_gemm<<<g64, 256, 0, s2>>>(p_bufB, Wg1, bg1, p_bufA, p_a16,
                                NN, 128, 64, GF_BIAS | GF_RELU | GF_NOC);  // 11
    k_gcn2_fused<<<tileBlocks, 256, 0, s2>>>(Wg2, bg2, emb);               // 12
    cudaEventRecord(evS2, s2);

    // ---- join ----
    cudaStreamWaitEvent(0, evS1, 0);
    cudaStreamWaitEvent(0, evS2, 0);
}

// round 11
// speedup vs baseline: 1.3352x; 1.3352x over previous
#include <cuda_runtime.h>
#include <cuda_fp16.h>
#include <cuda_bf16.h>

#define NN 50000
#define NE 800000
#define IND 128
#define HID 64

// ---------------- scratch (device globals; no runtime allocation) ----------
__device__ int    g_deg_in[NN];
__device__ int    g_deg_out[NN];
__device__ int    g_row_beg[NN];
__device__ int    g_cursor[NN];
__device__ int    g_total;
__device__ int    g_esrc[NE];
__device__ float  g_din[NN];
__device__ float  g_dout[NN];
__device__ float  g_h [NN * HID];     // fp32 (Laplacian base)
__device__ float  g_f1[NN * HID];     // fp32 (Laplacian base)
// fp16 tables (16B-aligned for uint4/ldmatrix paths)
__device__ __align__(16) __half g_in16 [NN * IND];
__device__ __align__(16) __half g_s16  [NN * HID];
__device__ __align__(16) __half g_h16  [NN * HID];
__device__ __align__(16) __half g_f116 [NN * HID];
__device__ __align__(16) __half g_a16  [NN * HID];
__device__ __align__(16) __half g_bufB16[NN * IND];
__device__ __align__(16) __half g_W1h [IND * HID];
__device__ __align__(16) __half g_W2h [HID * HID];
__device__ __align__(16) __half g_Wg1h[IND * HID];
__device__ __align__(16) __half g_Wg2h[HID * IND];

// ---------------- mma.sync helpers (HMMA m16n8k16, fp32 accum) -------------
__device__ __forceinline__ unsigned smem_u32(const void* p) {
    return (unsigned)__cvta_generic_to_shared(p);
}
__device__ __forceinline__ void ldsm4(unsigned r[4], unsigned addr) {
    asm volatile("ldmatrix.sync.aligned.m8n8.x4.shared.b16 {%0,%1,%2,%3}, [%4];"
                 : "=r"(r[0]), "=r"(r[1]), "=r"(r[2]), "=r"(r[3]) : "r"(addr));
}
__device__ __forceinline__ void ldsm4t(unsigned r[4], unsigned addr) {
    asm volatile("ldmatrix.sync.aligned.m8n8.x4.trans.shared.b16 {%0,%1,%2,%3}, [%4];"
                 : "=r"(r[0]), "=r"(r[1]), "=r"(r[2]), "=r"(r[3]) : "r"(addr));
}
__device__ __forceinline__ void mma16816(float d[4], const unsigned a[4],
                                         unsigned b0, unsigned b1) {
    asm volatile("mma.sync.aligned.m16n8k16.row.col.f32.f16.f16.f32 "
                 "{%0,%1,%2,%3}, {%4,%5,%6,%7}, {%8,%9}, {%0,%1,%2,%3};"
                 : "+f"(d[0]), "+f"(d[1]), "+f"(d[2]), "+f"(d[3])
                 : "r"(a[0]), "r"(a[1]), "r"(a[2]), "r"(a[3]), "r"(b0), "r"(b1));
}

// 64x64 output tile, 8 warps as 2(M)x4(N), each warp 32x16.
// As: [64][LDA] halves row-major; Bs: [K][LDB] halves row-major (k x n).
template<int LDA, int LDB>
__device__ __forceinline__ void mma_tile64(const __half* As, const __half* Bs, int K,
                                           float (&acc)[2][2][4], int lane, int warp) {
    int wm = (warp >> 2) * 32, wn = (warp & 3) * 16;
    #pragma unroll 2
    for (int k0 = 0; k0 < K; k0 += 16) {
        unsigned a[2][4], b[4];
        #pragma unroll
        for (int mi = 0; mi < 2; mi++) {
            unsigned ad = smem_u32(As + (wm + mi * 16 + (lane & 15)) * LDA
                                      + k0 + ((lane >> 4) << 3));
            ldsm4(a[mi], ad);
        }
        unsigned bd = smem_u32(Bs + (k0 + (lane & 15)) * LDB + wn + ((lane >> 4) << 3));
        ldsm4t(b, bd);
        #pragma unroll
        for (int mi = 0; mi < 2; mi++) {
            mma16816(acc[mi][0], a[mi], b[0], b[1]);
            mma16816(acc[mi][1], a[mi], b[2], b[3]);
        }
    }
}

// ---------------- graph prep ----------------
__global__ void k_zero_deg() {
    int i = blockIdx.x * blockDim.x + threadIdx.x;
    if (i < NN) { g_deg_in[i] = 0; g_deg_out[i] = 0; }
    if (i == 0) g_total = 0;
}

__global__ void k_deg(const int* __restrict__ src, const int* __restrict__ dst) {
    int e = blockIdx.x * blockDim.x + threadIdx.x;
    if (e < NE) {
        atomicAdd(&g_deg_in[dst[e]], 1);
        atomicAdd(&g_deg_out[src[e]], 1);
    }
}

__global__ void k_offsets() {
    int i = blockIdx.x * blockDim.x + threadIdx.x;
    if (i < NN) {
        int d = g_deg_in[i];
        int pos = atomicAdd(&g_total, d);
        g_row_beg[i] = pos;
        g_cursor[i]  = pos;
        g_din[i]  = rsqrtf((float)max(d, 1));
        g_dout[i] = rsqrtf((float)max(g_deg_out[i], 1));
    }
}

__global__ void k_scatter(const int* __restrict__ src, const int* __restrict__ dst) {
    int e = blockIdx.x * blockDim.x + threadIdx.x;
    if (e < NE) {
        int v = dst[e];
        int pos = atomicAdd(&g_cursor[v], 1);
        g_esrc[pos] = src[e];
    }
}

// ---------------- converts ----------------
__global__ void k_cvt(const float4* __restrict__ x, uint2* __restrict__ y, int n4) {
    int i = blockIdx.x * blockDim.x + threadIdx.x;
    if (i < n4) {
        float4 t = x[i];
        __half2 lo = __floats2half2_rn(t.x, t.y);
        __half2 hi = __floats2half2_rn(t.z, t.w);
        uint2 o;
        o.x = *reinterpret_cast<unsigned*>(&lo);
        o.y = *reinterpret_cast<unsigned*>(&hi);
        y[i] = o;
    }
}

__global__ void k_wcvt(const float* __restrict__ W1, const float* __restrict__ W2,
                       const float* __restrict__ Wg1, const float* __restrict__ Wg2) {
    int i = blockIdx.x * blockDim.x + threadIdx.x;
    if (i < IND * HID) g_W1h[i]  = __float2half(W1[i]);
    if (i < HID * HID) g_W2h[i]  = __float2half(W2[i]);
    if (i < IND * HID) g_Wg1h[i] = __float2half(Wg1[i]);
    if (i < HID * IND) g_Wg2h[i] = __float2half(Wg2[i]);
}

// ---------------- spmm, fp16 gather, fp32 accumulate (warp per node) -------
__global__ void k_spmm64h(const __half2* __restrict__ x16, const float* __restrict__ gsc,
                          const float* __restrict__ base, float* __restrict__ y,
                          __half2* __restrict__ y16, int mode) {
    int w = (blockIdx.x * blockDim.x + threadIdx.x) >> 5;
    int lane = threadIdx.x & 31;
    if (w >= NN) return;
    int beg = g_row_beg[w];
    int end = beg + g_deg_in[w];
    float2 acc = make_float2(0.f, 0.f);
    #pragma unroll 4
    for (int j = beg; j < end; j++) {
        int u = g_esrc[j];
        float s = gsc[u];
        float2 t = __half22float2(x16[u * 32 + lane]);
        acc.x += t.x * s;
        acc.y += t.y * s;
    }
    float sd = g_din[w];
    float2 r;
    if (mode) {
        float2 b = *reinterpret_cast<const float2*>(base + w * 64 + lane * 2);
        r.x = b.x - acc.x * sd;
        r.y = b.y - acc.y * sd;
    } else {
        r.x = acc.x * sd;
        r.y = acc.y * sd;
    }
    *reinterpret_cast<float2*>(y + w * 64 + lane * 2) = r;
    if (y16) y16[w * 32 + lane] = __floats2half2_rn(r.x, r.y);
}

// spmm over 128 dims; fp16 output only (feeds TC GEMM)
__global__ void k_spmm128h(const uint2* __restrict__ x16, const float* __restrict__ gsc,
                           __half* __restrict__ y16) {
    int w = (blockIdx.x * blockDim.x + threadIdx.x) >> 5;
    int lane = threadIdx.x & 31;
    if (w >= NN) return;
    int beg = g_row_beg[w];
    int end = beg + g_deg_in[w];
    float4 acc = make_float4(0.f, 0.f, 0.f, 0.f);
    #pragma unroll 4
    for (int j = beg; j < end; j++) {
        int u = g_esrc[j];
        float s = gsc[u];
        uint2 p = x16[u * 32 + lane];
        float2 lo = __half22float2(*reinterpret_cast<__half2*>(&p.x));
        float2 hi = __half22float2(*reinterpret_cast<__half2*>(&p.y));
        acc.x += lo.x * s; acc.y += lo.y * s;
        acc.z += hi.x * s; acc.w += hi.y * s;
    }
    float sd = g_din[w];
    __half2 a = __floats2half2_rn(acc.x * sd, acc.y * sd);
    __half2 b = __floats2half2_rn(acc.z * sd, acc.w * sd);
    uint2 o;
    o.x = *reinterpret_cast<unsigned*>(&a);
    o.y = *reinterpret_cast<unsigned*>(&b);
    *reinterpret_cast<uint2*>(y16 + (size_t)w * 128 + lane * 4) = o;
}

// ---------------- generic TC GEMM: 64 rows/block, N=64, K in {64,128} ------
#define GF_BIAS 2
#define GF_RELU 4
__global__ void __launch_bounds__(256)
k_gemm_tc(const __half* __restrict__ A, const __half* __restrict__ B,
          const float* __restrict__ bias, float* __restrict__ outf,
          __half* __restrict__ outh, int K, int flags) {
    __shared__ __half sA[64 * 136];
    __shared__ __half sB[128 * 72];
    int tid = threadIdx.x, lane = tid & 31, warp = tid >> 5;
    int rowBase = blockIdx.x * 64;
    int totalA = (K == 128) ? 1024 : 512;
    for (int l = tid; l < totalA; l += 256) {
        int row, unit;
        if (K == 128) { row = l >> 4; unit = l & 15; }
        else          { row = l >> 3; unit = l & 7; }
        uint4 v = make_uint4(0, 0, 0, 0);
        int gr = rowBase + row;
        if (gr < NN) v = *reinterpret_cast<const uint4*>(A + (size_t)gr * K + unit * 8);
        *reinterpret_cast<uint4*>(sA + row * 136 + unit * 8) = v;
    }
    for (int l = tid; l < K * 8; l += 256) {
        int row = l >> 3, unit = l & 7;
        *reinterpret_cast<uint4*>(sB + row * 72 + unit * 8) =
            *reinterpret_cast<const uint4*>(B + (size_t)row * 64 + unit * 8);
    }
    __syncthreads();
    float acc[2][2][4] = {};
    mma_tile64<136, 72>(sA, sB, K, acc, lane, warp);
    // epilogue
    int wm = (warp >> 2) * 32, wn = (warp & 3) * 16;
    #pragma unroll
    for (int mi = 0; mi < 2; mi++)
    #pragma unroll
    for (int ni = 0; ni < 2; ni++)
    #pragma unroll
    for (int h = 0; h < 2; h++) {
        int row = rowBase + wm + mi * 16 + (lane >> 2) + h * 8;
        if (row >= NN) continue;
        int col = wn + ni * 8 + (lane & 3) * 2;
        float v0 = acc[mi][ni][h * 2];
        float v1 = acc[mi][ni][h * 2 + 1];
        if (flags & GF_BIAS) { v0 += bias[col]; v1 += bias[col + 1]; }
        if (flags & GF_RELU) { v0 = fmaxf(v0, 0.f); v1 = fmaxf(v1, 0.f); }
        if (outf) *reinterpret_cast<float2*>(outf + (size_t)row * 64 + col) = make_float2(v0, v1);
        if (outh) {
            __half2 hv = __floats2half2_rn(v0, v1);
            *reinterpret_cast<__half2*>(outh + (size_t)row * 64 + col) = hv;
        }
    }
}

// ---------------- fused head (TC): gather f2 = L f1 in-block, then
//  out = relu(h@Wa + f1@Wb + f2@Wc + b3) @ W4 + b4  (Wa/Wb/Wc from W3) ------
__global__ void __launch_bounds__(256)
k_head_tc(const float* __restrict__ W3, const float* __restrict__ b3,
          const float* __restrict__ W4, const float* __restrict__ b4,
          float* __restrict__ out) {
    __shared__ __half F16[64 * 72];
    __shared__ __half Ab [64 * 72];
    __shared__ __half Bc [64 * 72];
    __shared__ float  Z  [64 * 68];
    int tid = threadIdx.x, lane = tid & 31, warp = tid >> 5;
    int rowBase = blockIdx.x * 64;

    // phase 1: gather f2 rows: f2[v] = f1[v] - din[v]*sum din[u]*f116[u]
    #pragma unroll 1
    for (int i = 0; i < 8; i++) {
        int row = warp * 8 + i;
        int v = rowBase + row;
        float2 r = make_float2(0.f, 0.f);
        if (v < NN) {
            int beg = g_row_beg[v], end = beg + g_deg_in[v];
            float2 acc = make_float2(0.f, 0.f);
            #pragma unroll 4
            for (int j = beg; j < end; j++) {
                int u = g_esrc[j];
                float s = g_din[u];
                float2 t = __half22float2(*reinterpret_cast<const __half2*>(g_f116 + u * 64 + lane * 2));
                acc.x += t.x * s;
                acc.y += t.y * s;
            }
            float sd = g_din[v];
            float2 b = *reinterpret_cast<const float2*>(g_f1 + (size_t)v * 64 + lane * 2);
            r.x = b.x - acc.x * sd;
            r.y = b.y - acc.y * sd;
        }
        *reinterpret_cast<__half2*>(F16 + row * 72 + lane * 2) = __floats2half2_rn(r.x, r.y);
    }

    // phase 2: 3-source TC GEMM accumulation
    float acc[2][2][4] = {};
    for (int s3 = 0; s3 < 3; s3++) {
        if (s3 < 2) {
            const __half* src = (s3 == 0) ? g_h16 : g_f116;
            for (int l = tid; l < 512; l += 256) {
                int row = l >> 3, unit = l & 7;
                int v = rowBase + row;
                uint4 val = make_uint4(0, 0, 0, 0);
                if (v < NN) val = *reinterpret_cast<const uint4*>(src + (size_t)v * 64 + unit * 8);
                *reinterpret_cast<uint4*>(Ab + row * 72 + unit * 8) = val;
            }
        }
        for (int l = tid; l < 2048; l += 256) {
            int k = l >> 5, c = (l & 31) * 2;
            float2 w0 = *reinterpret_cast<const float2*>(W3 + (size_t)k * 64 + c);
            float2 v;
            if (s3 == 0) {
                v = make_float2(3.f * w0.x, 3.f * w0.y);
            } else if (s3 == 1) {
                float2 w1  = *reinterpret_cast<const float2*>(W3 + (size_t)(64 + k) * 64 + c);
                float2 w3v = *reinterpret_cast<const float2*>(W3 + (size_t)(192 + k) * 64 + c);
                v = make_float2(-3.f * w0.x + 3.f * w1.x + w3v.x,
                                -3.f * w0.y + 3.f * w1.y + w3v.y);
            } else {
                float2 w1  = *reinterpret_cast<const float2*>(W3 + (size_t)(64 + k) * 64 + c);
                float2 w2  = *reinterpret_cast<const float2*>(W3 + (size_t)(128 + k) * 64 + c);
                float2 w4v = *reinterpret_cast<const float2*>(W3 + (size_t)(256 + k) * 64 + c);
                v = make_float2(0.75f * w0.x - 1.5f * w1.x + 0.75f * w2.x + w4v.x,
                                0.75f * w0.y - 1.5f * w1.y + 0.75f * w2.y + w4v.y);
            }
            *reinterpret_cast<__half2*>(Bc + k * 72 + c) = __floats2half2_rn(v.x, v.y);
        }
        __syncthreads();
        mma_tile64<72, 72>((s3 == 2) ? F16 : Ab, Bc, 64, acc, lane, warp);
        __syncthreads();
    }

    // epilogue: z = relu(acc + b3) -> Z smem
    int wm = (warp >> 2) * 32, wn = (warp & 3) * 16;
    #pragma unroll
    for (int mi = 0; mi < 2; mi++)
    #pragma unroll
    for (int ni = 0; ni < 2; ni++)
    #pragma unroll
    for (int h = 0; h < 2; h++) {
        int rl = wm + mi * 16 + (lane >> 2) + h * 8;
        int col = wn + ni * 8 + (lane & 3) * 2;
        float v0 = fmaxf(acc[mi][ni][h * 2]     + b3[col], 0.f);
        float v1 = fmaxf(acc[mi][ni][h * 2 + 1] + b3[col + 1], 0.f);
        Z[rl * 68 + col]     = v0;
        Z[rl * 68 + col + 1] = v1;
    }
    __syncthreads();

    // 64 -> 2 contraction with W4
    int rl = warp * 8 + (lane >> 2);
    int c0 = (lane & 3) * 16;
    float p0 = 0.f, p1 = 0.f;
    #pragma unroll
    for (int c = 0; c < 16; c++) {
        float z = Z[rl * 68 + c0 + c];
        p0 += z * W4[(c0 + c) * 2];
        p1 += z * W4[(c0 + c) * 2 + 1];
    }
    p0 += __shfl_down_sync(0xffffffffu, p0, 2, 4);
    p0 += __shfl_down_sync(0xffffffffu, p0, 1, 4);
    p1 += __shfl_down_sync(0xffffffffu, p1, 2, 4);
    p1 += __shfl_down_sync(0xffffffffu, p1, 1, 4);
    int row = rowBase + rl;
    if ((lane & 3) == 0 && row < NN) {
        out[row * 2]     = p0 + b4[0];
        out[row * 2 + 1] = p1 + b4[1];
    }
}

// ---------------- fused GCN tail (TC): gather din*sum(dout*a16) in-block,
//   then emb = A @ Wg2 + bg2 (N=128 via two 64-col passes) ------------------
__global__ void __launch_bounds__(256)
k_gcn2_tc(const float* __restrict__ bg2, float* __restrict__ emb) {
    __shared__ __half Ab[64 * 72];
    __shared__ __half Bw[64 * 136];
    int tid = threadIdx.x, lane = tid & 31, warp = tid >> 5;
    int rowBase = blockIdx.x * 64;

    // phase 1: gather
    #pragma unroll 1
    for (int i = 0; i < 8; i++) {
        int row = warp * 8 + i;
        int v = rowBase + row;
        float2 r = make_float2(0.f, 0.f);
        if (v < NN) {
            int beg = g_row_beg[v], end = beg + g_deg_in[v];
            float2 acc = make_float2(0.f, 0.f);
            #pragma unroll 4
            for (int j = beg; j < end; j++) {
                int u = g_esrc[j];
                float s = g_dout[u];
                float2 t = __half22float2(*reinterpret_cast<const __half2*>(g_a16 + u * 64 + lane * 2));
                acc.x += t.x * s;
                acc.y += t.y * s;
            }
            float sd = g_din[v];
            r.x = acc.x * sd;
            r.y = acc.y * sd;
        }
        *reinterpret_cast<__half2*>(Ab + row * 72 + lane * 2) = __floats2half2_rn(r.x, r.y);
    }
    // B: Wg2h [64][128]
    for (int l = tid; l < 1024; l += 256) {
        int row = l >> 4, unit = l & 15;
        *reinterpret_cast<uint4*>(Bw + row * 136 + unit * 8) =
            *reinterpret_cast<const uint4*>(g_Wg2h + (size_t)row * 128 + unit * 8);
    }
    __syncthreads();

    int wm = (warp >> 2) * 32, wn = (warp & 3) * 16;
    #pragma unroll 1
    for (int cb = 0; cb < 128; cb += 64) {
        float acc[2][2][4] = {};
        mma_tile64<72, 136>(Ab, Bw + cb, 64, acc, lane, warp);
        #pragma unroll
        for (int mi = 0; mi < 2; mi++)
        #pragma unroll
        for (int ni = 0; ni < 2; ni++)
        #pragma unroll
        for (int h = 0; h < 2; h++) {
            int row = rowBase + wm + mi * 16 + (lane >> 2) + h * 8;
            if (row >= NN) continue;
            int col = cb + wn + ni * 8 + (lane & 3) * 2;
            float v0 = acc[mi][ni][h * 2]     + bg2[col];
            float v1 = acc[mi][ni][h * 2 + 1] + bg2[col + 1];
            *reinterpret_cast<float2*>(emb + (size_t)row * 128 + col) = make_float2(v0, v1);
        }
    }
}

// ---------------- launch (two forked streams inside capture) ---------------
extern "C" void kernel_launch(void* const* d_in, const int* in_sizes, int n_in,
                              void* d_out, int out_size) {
    const float* in_feat = (const float*)d_in[0];
    const int*   src     = (const int*)d_in[1];
    const int*   dst     = (const int*)d_in[2];
    const float* W1 = (const float*)d_in[3];
    const float* b1 = (const float*)d_in[4];
    const float* W2 = (const float*)d_in[5];
    const float* b2 = (const float*)d_in[6];
    const float* W3 = (const float*)d_in[7];
    const float* b3 = (const float*)d_in[8];
    const float* W4 = (const float*)d_in[9];
    const float* b4 = (const float*)d_in[10];
    const float* Wg1 = (const float*)d_in[11];
    const float* bg1 = (const float*)d_in[12];
    const float* Wg2 = (const float*)d_in[13];
    const float* bg2 = (const float*)d_in[14];

    float* out = (float*)d_out;          // [NN,2]
    float* emb = out + NN * 2;           // [NN,128]

    float  *p_h, *p_f1, *p_din, *p_dout;
    __half *p_in16, *p_s16, *p_h16, *p_f116, *p_a16, *p_bufB16;
    __half *p_W1h, *p_W2h, *p_Wg1h;
    cudaGetSymbolAddress((void**)&p_h,     g_h);
    cudaGetSymbolAddress((void**)&p_f1,    g_f1);
    cudaGetSymbolAddress((void**)&p_din,   g_din);
    cudaGetSymbolAddress((void**)&p_dout,  g_dout);
    cudaGetSymbolAddress((void**)&p_in16,  g_in16);
    cudaGetSymbolAddress((void**)&p_s16,   g_s16);
    cudaGetSymbolAddress((void**)&p_h16,   g_h16);
    cudaGetSymbolAddress((void**)&p_f116,  g_f116);
    cudaGetSymbolAddress((void**)&p_a16,   g_a16);
    cudaGetSymbolAddress((void**)&p_bufB16, g_bufB16);
    cudaGetSymbolAddress((void**)&p_W1h,   g_W1h);
    cudaGetSymbolAddress((void**)&p_W2h,   g_W2h);
    cudaGetSymbolAddress((void**)&p_Wg1h,  g_Wg1h);

    // streams/events created once on the uncaptured correctness call; reused
    // during capture (creation during capture is illegal). Same work per call.
    static cudaStream_t s1 = nullptr, s2 = nullptr;
    static cudaEvent_t evRoot, evGraph, evCvt, evW, evS1, evS2;
    if (!s1) {
        cudaStreamCreateWithFlags(&s1, cudaStreamNonBlocking);
        cudaStreamCreateWithFlags(&s2, cudaStreamNonBlocking);
        cudaEventCreateWithFlags(&evRoot,  cudaEventDisableTiming);
        cudaEventCreateWithFlags(&evGraph, cudaEventDisableTiming);
        cudaEventCreateWithFlags(&evCvt,   cudaEventDisableTiming);
        cudaEventCreateWithFlags(&evW,     cudaEventDisableTiming);
        cudaEventCreateWithFlags(&evS1,    cudaEventDisableTiming);
        cudaEventCreateWithFlags(&evS2,    cudaEventDisableTiming);
    }

    const int TB = 256;
    int nBlkN = (NN + TB - 1) / TB;
    int nBlkE = (NE + TB - 1) / TB;
    int spmmBlocks = (NN * 32 + TB - 1) / TB;
    int tileBlocks = (NN + 63) / 64;

    // ---- fork ----
    cudaEventRecord(evRoot, 0);
    cudaStreamWaitEvent(s1, evRoot, 0);
    cudaStreamWaitEvent(s2, evRoot, 0);

    // Submission order keeps a TC GEMM at launch slot #4 for ncu (-s 5 -c 1).
    k_zero_deg<<<nBlkN, TB>>>();                                              // 1
    k_cvt<<<(NN * 32 + TB - 1) / TB, TB, 0, s1>>>((const float4*)in_feat,
                                                  (uint2*)p_in16, NN * 32);   // 2
    k_wcvt<<<(IND * HID + TB - 1) / TB, TB, 0, s1>>>(W1, W2, Wg1, Wg2);       // 3
    cudaEventRecord(evCvt, s1);
    cudaEventRecord(evW, s1);
    k_gemm_tc<<<tileBlocks, 256, 0, s1>>>(p_in16, p_W1h, b1, nullptr, p_s16,
                                          128, GF_BIAS | GF_RELU);            // 4 (profiled)
    k_gemm_tc<<<tileBlocks, 256, 0, s1>>>(p_s16, p_W2h, b2, p_h, p_h16,
                                          64, GF_BIAS | GF_RELU);             // 5
    k_deg<<<nBlkE, TB>>>(src, dst);                                           // 6
    k_offsets<<<nBlkN, TB>>>();                                               // 7
    k_scatter<<<nBlkE, TB>>>(src, dst);                                       // 8
    cudaEventRecord(evGraph, 0);

    // ---- s1: band branch (needs graph) ----
    cudaStreamWaitEvent(s1, evGraph, 0);
    k_spmm64h<<<spmmBlocks, TB, 0, s1>>>((const __half2*)p_h16, p_din, p_h,
                                         p_f1, (__half2*)p_f116, 1);          // 9
    k_head_tc<<<tileBlocks, 256, 0, s1>>>(W3, b3, W4, b4, out);               // 10
    cudaEventRecord(evS1, s1);

    // ---- s2: GCN branch (needs graph + in16 + weights) ----
    cudaStreamWaitEvent(s2, evGraph, 0);
    cudaStreamWaitEvent(s2, evCvt, 0);
    k_spmm128h<<<spmmBlocks, TB, 0, s2>>>((const uint2*)p_in16, p_dout, p_bufB16); // 11
    cudaStreamWaitEvent(s2, evW, 0);
    k_gemm_tc<<<tileBlocks, 256, 0, s2>>>(p_bufB16, p_Wg1h, bg1, nullptr, p_a16,
                                          128, GF_BIAS | GF_RELU);            // 12
    k_gcn2_tc<<<tileBlocks, 256, 0, s2>>>(bg2, emb);                          // 13
    cudaEventRecord(evS2, s2);

    // ---- join ----
    cudaStreamWaitEvent(0, evS1, 0);
    cudaStreamWaitEvent(0, evS2, 0);
}

// round 14
// speedup vs baseline: 1.3719x; 1.0275x over previous
#include <cuda_runtime.h>
#include <cuda_fp16.h>
#include <cuda_bf16.h>

#define NN 50000
#define NE 800000
#define IND 128
#define HID 64

// ---------------- scratch (device globals; no runtime allocation) ----------
__device__ int    g_deg_in[NN];
__device__ int    g_deg_out[NN];
__device__ int    g_row_beg[NN];
__device__ int    g_cursor[NN];
__device__ int    g_total;
__device__ int    g_esrc[NE];
__device__ float  g_din[NN];
__device__ float  g_dout[NN];
__device__ float  g_h [NN * HID];     // fp32 (Laplacian base)
__device__ float  g_f1[NN * HID];     // fp32 (Laplacian base)
// fp16 tables (16B-aligned for uint4/ldmatrix paths)
__device__ __align__(16) __half g_in16 [NN * IND];
__device__ __align__(16) __half g_h16  [NN * HID];
__device__ __align__(16) __half g_f116 [NN * HID];
__device__ __align__(16) __half g_a16  [NN * HID];
__device__ __align__(16) __half g_W1h [IND * HID];
__device__ __align__(16) __half g_W2h [HID * HID];
__device__ __align__(16) __half g_Wg1h[IND * HID];
__device__ __align__(16) __half g_Wg2h[HID * IND];

// ---------------- mma.sync helpers (HMMA m16n8k16, fp32 accum) -------------
__device__ __forceinline__ unsigned smem_u32(const void* p) {
    return (unsigned)__cvta_generic_to_shared(p);
}
__device__ __forceinline__ void ldsm4(unsigned r[4], unsigned addr) {
    asm volatile("ldmatrix.sync.aligned.m8n8.x4.shared.b16 {%0,%1,%2,%3}, [%4];"
                 : "=r"(r[0]), "=r"(r[1]), "=r"(r[2]), "=r"(r[3]) : "r"(addr));
}
__device__ __forceinline__ void ldsm4t(unsigned r[4], unsigned addr) {
    asm volatile("ldmatrix.sync.aligned.m8n8.x4.trans.shared.b16 {%0,%1,%2,%3}, [%4];"
                 : "=r"(r[0]), "=r"(r[1]), "=r"(r[2]), "=r"(r[3]) : "r"(addr));
}
__device__ __forceinline__ void mma16816(float d[4], const unsigned a[4],
                                         unsigned b0, unsigned b1) {
    asm volatile("mma.sync.aligned.m16n8k16.row.col.f32.f16.f16.f32 "
                 "{%0,%1,%2,%3}, {%4,%5,%6,%7}, {%8,%9}, {%0,%1,%2,%3};"
                 : "+f"(d[0]), "+f"(d[1]), "+f"(d[2]), "+f"(d[3])
                 : "r"(a[0]), "r"(a[1]), "r"(a[2]), "r"(a[3]), "r"(b0), "r"(b1));
}

// 64x64 output tile, 8 warps as 2(M)x4(N), each warp 32x16.
// As: [64][LDA] halves row-major; Bs: [K][LDB] halves row-major (k x n).
template<int LDA, int LDB>
__device__ __forceinline__ void mma_tile64(const __half* As, const __half* Bs, int K,
                                           float (&acc)[2][2][4], int lane, int warp) {
    int wm = (warp >> 2) * 32, wn = (warp & 3) * 16;
    #pragma unroll
    for (int k0 = 0; k0 < K; k0 += 16) {
        unsigned a[2][4], b[4];
        #pragma unroll
        for (int mi = 0; mi < 2; mi++) {
            unsigned ad = smem_u32(As + (wm + mi * 16 + (lane & 15)) * LDA
                                      + k0 + ((lane >> 4) << 3));
            ldsm4(a[mi], ad);
        }
        unsigned bd = smem_u32(Bs + (k0 + (lane & 15)) * LDB + wn + ((lane >> 4) << 3));
        ldsm4t(b, bd);
        #pragma unroll
        for (int mi = 0; mi < 2; mi++) {
            mma16816(acc[mi][0], a[mi], b[0], b[1]);
            mma16816(acc[mi][1], a[mi], b[2], b[3]);
        }
    }
}

// ---------------- graph prep ----------------
__global__ void k_zero_deg() {
    int i = blockIdx.x * blockDim.x + threadIdx.x;
    if (i < NN) { g_deg_in[i] = 0; g_deg_out[i] = 0; }
    if (i == 0) g_total = 0;
}

__global__ void k_deg(const int* __restrict__ src, const int* __restrict__ dst) {
    int e = blockIdx.x * blockDim.x + threadIdx.x;
    if (e < NE) {
        atomicAdd(&g_deg_in[dst[e]], 1);
        atomicAdd(&g_deg_out[src[e]], 1);
    }
}

__global__ void k_offsets() {
    int i = blockIdx.x * blockDim.x + threadIdx.x;
    if (i < NN) {
        int d = g_deg_in[i];
        int pos = atomicAdd(&g_total, d);
        g_row_beg[i] = pos;
        g_cursor[i]  = pos;
        g_din[i]  = rsqrtf((float)max(d, 1));
        g_dout[i] = rsqrtf((float)max(g_deg_out[i], 1));
    }
}

__global__ void k_scatter(const int* __restrict__ src, const int* __restrict__ dst) {
    int e = blockIdx.x * blockDim.x + threadIdx.x;
    if (e < NE) {
        int v = dst[e];
        int pos = atomicAdd(&g_cursor[v], 1);
        g_esrc[pos] = src[e];
    }
}

// ---------------- converts ----------------
__global__ void k_cvt(const float4* __restrict__ x, uint2* __restrict__ y, int n4) {
    int i = blockIdx.x * blockDim.x + threadIdx.x;
    if (i < n4) {
        float4 t = x[i];
        __half2 lo = __floats2half2_rn(t.x, t.y);
        __half2 hi = __floats2half2_rn(t.z, t.w);
        uint2 o;
        o.x = *reinterpret_cast<unsigned*>(&lo);
        o.y = *reinterpret_cast<unsigned*>(&hi);
        y[i] = o;
    }
}

__global__ void k_wcvt(const float* __restrict__ W1, const float* __restrict__ W2,
                       const float* __restrict__ Wg1, const float* __restrict__ Wg2) {
    int i = blockIdx.x * blockDim.x + threadIdx.x;
    if (i < IND * HID) g_W1h[i]  = __float2half(W1[i]);
    if (i < HID * HID) g_W2h[i]  = __float2half(W2[i]);
    if (i < IND * HID) g_Wg1h[i] = __float2half(Wg1[i]);
    if (i < HID * IND) g_Wg2h[i] = __float2half(Wg2[i]);
}

// ---------------- spmm, fp16 gather, fp32 accumulate (warp per node) -------
__global__ void k_spmm64h(const __half2* __restrict__ x16, const float* __restrict__ gsc,
                          const float* __restrict__ base, float* __restrict__ y,
                          __half2* __restrict__ y16, int mode) {
    int w = (blockIdx.x * blockDim.x + threadIdx.x) >> 5;
    int lane = threadIdx.x & 31;
    if (w >= NN) return;
    int beg = g_row_beg[w];
    int end = beg + g_deg_in[w];
    float2 acc = make_float2(0.f, 0.f);
    #pragma unroll 4
    for (int j = beg; j < end; j++) {
        int u = g_esrc[j];
        float s = gsc[u];
        float2 t = __half22float2(x16[u * 32 + lane]);
        acc.x += t.x * s;
        acc.y += t.y * s;
    }
    float sd = g_din[w];
    float2 r;
    if (mode) {
        float2 b = *reinterpret_cast<const float2*>(base + w * 64 + lane * 2);
        r.x = b.x - acc.x * sd;
        r.y = b.y - acc.y * sd;
    } else {
        r.x = acc.x * sd;
        r.y = acc.y * sd;
    }
    *reinterpret_cast<float2*>(y + w * 64 + lane * 2) = r;
    if (y16) y16[w * 32 + lane] = __floats2half2_rn(r.x, r.y);
}

// ---------------- fused MLP: h = relu(relu(in16@W1+b1)@W2+b2) --------------
__global__ void __launch_bounds__(256)
k_mlp_tc(const float* __restrict__ b1, const float* __restrict__ b2,
         float* __restrict__ hf, __half* __restrict__ hh) {
    __shared__ __half sA[64 * 136];
    __shared__ __half sB[128 * 72];
    __shared__ __half sT[64 * 72];
    int tid = threadIdx.x, lane = tid & 31, warp = tid >> 5;
    int rowBase = blockIdx.x * 64;
    int wm = (warp >> 2) * 32, wn = (warp & 3) * 16;

    // A: in16 64 rows x 128
    for (int l = tid; l < 1024; l += 256) {
        int row = l >> 4, unit = l & 15;
        uint4 v = make_uint4(0, 0, 0, 0);
        int gr = rowBase + row;
        if (gr < NN) v = *reinterpret_cast<const uint4*>(g_in16 + (size_t)gr * 128 + unit * 8);
        *reinterpret_cast<uint4*>(sA + row * 136 + unit * 8) = v;
    }
    // B: W1h [128][64]
    for (int l = tid; l < 1024; l += 256) {
        int row = l >> 3, unit = l & 7;
        *reinterpret_cast<uint4*>(sB + row * 72 + unit * 8) =
            *reinterpret_cast<const uint4*>(g_W1h + (size_t)row * 64 + unit * 8);
    }
    __syncthreads();
    float acc[2][2][4] = {};
    mma_tile64<136, 72>(sA, sB, 128, acc, lane, warp);
    // epilogue 1: relu+b1 -> sT (fp16)
    #pragma unroll
    for (int mi = 0; mi < 2; mi++)
    #pragma unroll
    for (int ni = 0; ni < 2; ni++)
    #pragma unroll
    for (int h = 0; h < 2; h++) {
        int rl = wm + mi * 16 + (lane >> 2) + h * 8;
        int col = wn + ni * 8 + (lane & 3) * 2;
        float v0 = fmaxf(acc[mi][ni][h * 2]     + b1[col], 0.f);
        float v1 = fmaxf(acc[mi][ni][h * 2 + 1] + b1[col + 1], 0.f);
        *reinterpret_cast<__half2*>(sT + rl * 72 + col) = __floats2half2_rn(v0, v1);
    }
    __syncthreads();   // mma reads of sB done + sT complete
    // B: W2h [64][64]
    for (int l = tid; l < 512; l += 256) {
        int row = l >> 3, unit = l & 7;
        *reinterpret_cast<uint4*>(sB + row * 72 + unit * 8) =
            *reinterpret_cast<const uint4*>(g_W2h + (size_t)row * 64 + unit * 8);
    }
    __syncthreads();
    float acc2[2][2][4] = {};
    mma_tile64<72, 72>(sT, sB, 64, acc2, lane, warp);
    // epilogue 2: relu+b2 -> g_h (fp32) + g_h16
    #pragma unroll
    for (int mi = 0; mi < 2; mi++)
    #pragma unroll
    for (int ni = 0; ni < 2; ni++)
    #pragma unroll
    for (int h = 0; h < 2; h++) {
        int row = rowBase + wm + mi * 16 + (lane >> 2) + h * 8;
        if (row >= NN) continue;
        int col = wn + ni * 8 + (lane & 3) * 2;
        float v0 = fmaxf(acc2[mi][ni][h * 2]     + b2[col], 0.f);
        float v1 = fmaxf(acc2[mi][ni][h * 2 + 1] + b2[col + 1], 0.f);
        *reinterpret_cast<float2*>(hf + (size_t)row * 64 + col) = make_float2(v0, v1);
        *reinterpret_cast<__half2*>(hh + (size_t)row * 64 + col) = __floats2half2_rn(v0, v1);
    }
}

// ---------------- fused GCN conv1: gather din*sum(dout*in16) (128-dim)
//   in-block, then a16 = relu(gather @ Wg1 + bg1) ---------------------------
__global__ void __launch_bounds__(256)
k_gcn1_tc(const float* __restrict__ bg1, __half* __restrict__ a16) {
    __shared__ __half sA[64 * 136];
    __shared__ __half sB[128 * 72];
    int tid = threadIdx.x, lane = tid & 31, warp = tid >> 5;
    int rowBase = blockIdx.x * 64;

    // phase 1: gather 128-dim rows
    #pragma unroll 1
    for (int i = 0; i < 8; i++) {
        int row = warp * 8 + i;
        int v = rowBase + row;
        float4 acc = make_float4(0.f, 0.f, 0.f, 0.f);
        float sd = 0.f;
        if (v < NN) {
            int beg = g_row_beg[v], end = beg + g_deg_in[v];
            #pragma unroll 4
            for (int j = beg; j < end; j++) {
                int u = g_esrc[j];
                float s = g_dout[u];
                uint2 p = *reinterpret_cast<const uint2*>(g_in16 + (size_t)u * 128 + lane * 4);
                float2 lo = __half22float2(*reinterpret_cast<__half2*>(&p.x));
                float2 hi = __half22float2(*reinterpret_cast<__half2*>(&p.y));
                acc.x += lo.x * s; acc.y += lo.y * s;
                acc.z += hi.x * s; acc.w += hi.y * s;
            }
            sd = g_din[v];
        }
        __half2 a = __floats2half2_rn(acc.x * sd, acc.y * sd);
        __half2 b = __floats2half2_rn(acc.z * sd, acc.w * sd);
        uint2 o;
        o.x = *reinterpret_cast<unsigned*>(&a);
        o.y = *reinterpret_cast<unsigned*>(&b);
        *reinterpret_cast<uint2*>(sA + row * 136 + lane * 4) = o;
    }
    // B: Wg1h [128][64]
    for (int l = tid; l < 1024; l += 256) {
        int row = l >> 3, unit = l & 7;
        *reinterpret_cast<uint4*>(sB + row * 72 + unit * 8) =
            *reinterpret_cast<const uint4*>(g_Wg1h + (size_t)row * 64 + unit * 8);
    }
    __syncthreads();
    float acc[2][2][4] = {};
    mma_tile64<136, 72>(sA, sB, 128, acc, lane, warp);
    int wm = (warp >> 2) * 32, wn = (warp & 3) * 16;
    #pragma unroll
    for (int mi = 0; mi < 2; mi++)
    #pragma unroll
    for (int ni = 0; ni < 2; ni++)
    #pragma unroll
    for (int h = 0; h < 2; h++) {
        int row = rowBase + wm + mi * 16 + (lane >> 2) + h * 8;
        if (row >= NN) continue;
        int col = wn + ni * 8 + (lane & 3) * 2;
        float v0 = fmaxf(acc[mi][ni][h * 2]     + bg1[col], 0.f);
        float v1 = fmaxf(acc[mi][ni][h * 2 + 1] + bg1[col + 1], 0.f);
        *reinterpret_cast<__half2*>(a16 + (size_t)row * 64 + col) = __floats2half2_rn(v0, v1);
    }
}

// ---------------- fused head (TC): gather f2 = L f1 in-block, then
//  out = relu(h@Wa + f1@Wb + f2@Wc + b3) @ W4 + b4  (Wa/Wb/Wc from W3) ------
__global__ void __launch_bounds__(256)
k_head_tc(const float* __restrict__ W3, const float* __restrict__ b3,
          const float* __restrict__ W4, const float* __restrict__ b4,
          float* __restrict__ out) {
    __shared__ __half F16[64 * 72];
    __shared__ __half Ab [64 * 72];
    __shared__ __half Bc [64 * 72];
    __shared__ float  Z  [64 * 68];
    int tid = threadIdx.x, lane = tid & 31, warp = tid >> 5;
    int rowBase = blockIdx.x * 64;

    // phase 1: gather f2 rows: f2[v] = f1[v] - din[v]*sum din[u]*f116[u]
    #pragma unroll 1
    for (int i = 0; i < 8; i++) {
        int row = warp * 8 + i;
        int v = rowBase + row;
        float2 r = make_float2(0.f, 0.f);
        if (v < NN) {
            int beg = g_row_beg[v], end = beg + g_deg_in[v];
            float2 acc = make_float2(0.f, 0.f);
            #pragma unroll 4
            for (int j = beg; j < end; j++) {
                int u = g_esrc[j];
                float s = g_din[u];
                float2 t = __half22float2(*reinterpret_cast<const __half2*>(g_f116 + u * 64 + lane * 2));
                acc.x += t.x * s;
                acc.y += t.y * s;
            }
            float sd = g_din[v];
            float2 b = *reinterpret_cast<const float2*>(g_f1 + (size_t)v * 64 + lane * 2);
            r.x = b.x - acc.x * sd;
            r.y = b.y - acc.y * sd;
        }
        *reinterpret_cast<__half2*>(F16 + row * 72 + lane * 2) = __floats2half2_rn(r.x, r.y);
    }

    // phase 2: 3-source TC GEMM accumulation
    float acc[2][2][4] = {};
    for (int s3 = 0; s3 < 3; s3++) {
        if (s3 < 2) {
            const __half* src = (s3 == 0) ? g_h16 : g_f116;
            for (int l = tid; l < 512; l += 256) {
                int row = l >> 3, unit = l & 7;
                int v = rowBase + row;
                uint4 val = make_uint4(0, 0, 0, 0);
                if (v < NN) val = *reinterpret_cast<const uint4*>(src + (size_t)v * 64 + unit * 8);
                *reinterpret_cast<uint4*>(Ab + row * 72 + unit * 8) = val;
            }
        }
        for (int l = tid; l < 2048; l += 256) {
            int k = l >> 5, c = (l & 31) * 2;
            float2 w0 = *reinterpret_cast<const float2*>(W3 + (size_t)k * 64 + c);
            float2 v;
            if (s3 == 0) {
                v = make_float2(3.f * w0.x, 3.f * w0.y);
            } else if (s3 == 1) {
                float2 w1  = *reinterpret_cast<const float2*>(W3 + (size_t)(64 + k) * 64 + c);
                float2 w3v = *reinterpret_cast<const float2*>(W3 + (size_t)(192 + k) * 64 + c);
                v = make_float2(-3.f * w0.x + 3.f * w1.x + w3v.x,
                                -3.f * w0.y + 3.f * w1.y + w3v.y);
            } else {
                float2 w1  = *reinterpret_cast<const float2*>(W3 + (size_t)(64 + k) * 64 + c);
                float2 w2  = *reinterpret_cast<const float2*>(W3 + (size_t)(128 + k) * 64 + c);
                float2 w4v = *reinterpret_cast<const float2*>(W3 + (size_t)(256 + k) * 64 + c);
                v = make_float2(0.75f * w0.x - 1.5f * w1.x + 0.75f * w2.x + w4v.x,
                                0.75f * w0.y - 1.5f * w1.y + 0.75f * w2.y + w4v.y);
            }
            *reinterpret_cast<__half2*>(Bc + k * 72 + c) = __floats2half2_rn(v.x, v.y);
        }
        __syncthreads();
        mma_tile64<72, 72>((s3 == 2) ? F16 : Ab, Bc, 64, acc, lane, warp);
        __syncthreads();
    }

    // epilogue: z = relu(acc + b3) -> Z smem
    int wm = (warp >> 2) * 32, wn = (warp & 3) * 16;
    #pragma unroll
    for (int mi = 0; mi < 2; mi++)
    #pragma unroll
    for (int ni = 0; ni < 2; ni++)
    #pragma unroll
    for (int h = 0; h < 2; h++) {
        int rl = wm + mi * 16 + (lane >> 2) + h * 8;
        int col = wn + ni * 8 + (lane & 3) * 2;
        float v0 = fmaxf(acc[mi][ni][h * 2]     + b3[col], 0.f);
        float v1 = fmaxf(acc[mi][ni][h * 2 + 1] + b3[col + 1], 0.f);
        Z[rl * 68 + col]     = v0;
        Z[rl * 68 + col + 1] = v1;
    }
    __syncthreads();

    // 64 -> 2 contraction with W4
    int rl = warp * 8 + (lane >> 2);
    int c0 = (lane & 3) * 16;
    float p0 = 0.f, p1 = 0.f;
    #pragma unroll
    for (int c = 0; c < 16; c++) {
        float z = Z[rl * 68 + c0 + c];
        p0 += z * W4[(c0 + c) * 2];
        p1 += z * W4[(c0 + c) * 2 + 1];
    }
    p0 += __shfl_down_sync(0xffffffffu, p0, 2, 4);
    p0 += __shfl_down_sync(0xffffffffu, p0, 1, 4);
    p1 += __shfl_down_sync(0xffffffffu, p1, 2, 4);
    p1 += __shfl_down_sync(0xffffffffu, p1, 1, 4);
    int row = rowBase + rl;
    if ((lane & 3) == 0 && row < NN) {
        out[row * 2]     = p0 + b4[0];
        out[row * 2 + 1] = p1 + b4[1];
    }
}

// ---------------- fused GCN tail (TC): gather din*sum(dout*a16) in-block,
//   then emb = A @ Wg2 + bg2 (N=128 via two 64-col passes) ------------------
__global__ void __launch_bounds__(256)
k_gcn2_tc(const float* __restrict__ bg2, float* __restrict__ emb) {
    __shared__ __half Ab[64 * 72];
    __shared__ __half Bw[64 * 136];
    int tid = threadIdx.x, lane = tid & 31, warp = tid >> 5;
    int rowBase = blockIdx.x * 64;

    // phase 1: gather
    #pragma unroll 1
    for (int i = 0; i < 8; i++) {
        int row = warp * 8 + i;
        int v = rowBase + row;
        float2 r = make_float2(0.f, 0.f);
        if (v < NN) {
            int beg = g_row_beg[v], end = beg + g_deg_in[v];
            float2 acc = make_float2(0.f, 0.f);
            #pragma unroll 4
            for (int j = beg; j < end; j++) {
                int u = g_esrc[j];
                float s = g_dout[u];
                float2 t = __half22float2(*reinterpret_cast<const __half2*>(g_a16 + u * 64 + lane * 2));
                acc.x += t.x * s;
                acc.y += t.y * s;
            }
            float sd = g_din[v];
            r.x = acc.x * sd;
            r.y = acc.y * sd;
        }
        *reinterpret_cast<__half2*>(Ab + row * 72 + lane * 2) = __floats2half2_rn(r.x, r.y);
    }
    // B: Wg2h [64][128]
    for (int l = tid; l < 1024; l += 256) {
        int row = l >> 4, unit = l & 15;
        *reinterpret_cast<uint4*>(Bw + row * 136 + unit * 8) =
            *reinterpret_cast<const uint4*>(g_Wg2h + (size_t)row * 128 + unit * 8);
    }
    __syncthreads();

    int wm = (warp >> 2) * 32, wn = (warp & 3) * 16;
    #pragma unroll 1
    for (int cb = 0; cb < 128; cb += 64) {
        float acc[2][2][4] = {};
        mma_tile64<72, 136>(Ab, Bw + cb, 64, acc, lane, warp);
        #pragma unroll
        for (int mi = 0; mi < 2; mi++)
        #pragma unroll
        for (int ni = 0; ni < 2; ni++)
        #pragma unroll
        for (int h = 0; h < 2; h++) {
            int row = rowBase + wm + mi * 16 + (lane >> 2) + h * 8;
            if (row >= NN) continue;
            int col = cb + wn + ni * 8 + (lane & 3) * 2;
            float v0 = acc[mi][ni][h * 2]     + bg2[col];
            float v1 = acc[mi][ni][h * 2 + 1] + bg2[col + 1];
            *reinterpret_cast<float2*>(emb + (size_t)row * 128 + col) = make_float2(v0, v1);
        }
    }
}

// ---------------- launch (two forked streams inside capture) ---------------
extern "C" void kernel_launch(void* const* d_in, const int* in_sizes, int n_in,
                              void* d_out, int out_size) {
    const float* in_feat = (const float*)d_in[0];
    const int*   src     = (const int*)d_in[1];
    const int*   dst     = (const int*)d_in[2];
    const float* W1 = (const float*)d_in[3];
    const float* b1 = (const float*)d_in[4];
    const float* W2 = (const float*)d_in[5];
    const float* b2 = (const float*)d_in[6];
    const float* W3 = (const float*)d_in[7];
    const float* b3 = (const float*)d_in[8];
    const float* W4 = (const float*)d_in[9];
    const float* b4 = (const float*)d_in[10];
    const float* Wg1 = (const float*)d_in[11];
    const float* bg1 = (const float*)d_in[12];
    const float* Wg2 = (const float*)d_in[13];
    const float* bg2 = (const float*)d_in[14];

    float* out = (float*)d_out;          // [NN,2]
    float* emb = out + NN * 2;           // [NN,128]

    float  *p_h, *p_f1, *p_din;
    __half *p_in16, *p_h16, *p_f116, *p_a16;
    cudaGetSymbolAddress((void**)&p_h,    g_h);
    cudaGetSymbolAddress((void**)&p_f1,   g_f1);
    cudaGetSymbolAddress((void**)&p_din,  g_din);
    cudaGetSymbolAddress((void**)&p_in16, g_in16);
    cudaGetSymbolAddress((void**)&p_h16,  g_h16);
    cudaGetSymbolAddress((void**)&p_f116, g_f116);
    cudaGetSymbolAddress((void**)&p_a16,  g_a16);

    // streams/events created once on the uncaptured correctness call; reused
    // during capture (creation during capture is illegal). Same work per call.
    static cudaStream_t s1 = nullptr, s2 = nullptr;
    static cudaEvent_t evRoot, evGraph, evCvt, evS1, evS2;
    if (!s1) {
        cudaStreamCreateWithFlags(&s1, cudaStreamNonBlocking);
        cudaStreamCreateWithFlags(&s2, cudaStreamNonBlocking);
        cudaEventCreateWithFlags(&evRoot,  cudaEventDisableTiming);
        cudaEventCreateWithFlags(&evGraph, cudaEventDisableTiming);
        cudaEventCreateWithFlags(&evCvt,   cudaEventDisableTiming);
        cudaEventCreateWithFlags(&evS1,    cudaEventDisableTiming);
        cudaEventCreateWithFlags(&evS2,    cudaEventDisableTiming);
    }

    const int TB = 256;
    int nBlkN = (NN + TB - 1) / TB;
    int nBlkE = (NE + TB - 1) / TB;
    int spmmBlocks = (NN * 32 + TB - 1) / TB;
    int tileBlocks = (NN + 63) / 64;

    // ---- fork ----
    cudaEventRecord(evRoot, 0);
    cudaStreamWaitEvent(s1, evRoot, 0);
    cudaStreamWaitEvent(s2, evRoot, 0);

    // Submission order keeps the fused MLP at launch slot #4 for ncu.
    k_zero_deg<<<nBlkN, TB>>>();                                              // 1
    k_cvt<<<(NN * 32 + TB - 1) / TB, TB, 0, s1>>>((const float4*)in_feat,
                                                  (uint2*)p_in16, NN * 32);   // 2
    k_wcvt<<<(IND * HID + TB - 1) / TB, TB, 0, s1>>>(W1, W2, Wg1, Wg2);       // 3
    cudaEventRecord(evCvt, s1);
    k_mlp_tc<<<tileBlocks, 256, 0, s1>>>(b1, b2, p_h, p_h16);                 // 4 (profiled)
    k_deg<<<nBlkE, TB>>>(src, dst);                                           // 5
    k_offsets<<<nBlkN, TB>>>();                                               // 6
    k_scatter<<<nBlkE, TB>>>(src, dst);                                       // 7
    cudaEventRecord(evGraph, 0);

    // ---- s1: band branch (needs graph) ----
    cudaStreamWaitEvent(s1, evGraph, 0);
    k_spmm64h<<<spmmBlocks, TB, 0, s1>>>((const __half2*)p_h16, p_din, p_h,
                                         p_f1, (__half2*)p_f116, 1);          // 8
    k_head_tc<<<tileBlocks, 256, 0, s1>>>(W3, b3, W4, b4, out);               // 9
    cudaEventRecord(evS1, s1);

    // ---- s2: GCN branch (needs graph + in16 + weights) ----
    cudaStreamWaitEvent(s2, evGraph, 0);
    cudaStreamWaitEvent(s2, evCvt, 0);
    k_gcn1_tc<<<tileBlocks, 256, 0, s2>>>(bg1, p_a16);                        // 10
    k_gcn2_tc<<<tileBlocks, 256, 0, s2>>>(bg2, emb);                          // 11
    cudaEventRecord(evS2, s2);

    // ---- join ----
    cudaStreamWaitEvent(0, evS1, 0);
    cudaStreamWaitEvent(0, evS2, 0);
}

// round 17
// speedup vs baseline: 1.4031x; 1.0227x over previous
#include <cuda_runtime.h>
#include <cuda_fp16.h>
#include <cuda_bf16.h>

#define NN 50000
#define NE 800000
#define IND 128
#define HID 64

// ---------------- scratch (device globals; no runtime allocation) ----------
__device__ int    g_deg_in[NN];
__device__ int    g_deg_out[NN];
__device__ int    g_row_beg[NN];
__device__ int    g_cursor[NN];
__device__ int    g_total;
__device__ int    g_esrc[NE];
__device__ float  g_din[NN];
__device__ float  g_dout[NN];
__device__ float  g_h [NN * HID];     // fp32 (Laplacian base)
__device__ float  g_f1[NN * HID];     // fp32 (Laplacian base)
// fp16 tables (16B-aligned for uint4/ldmatrix paths)
__device__ __align__(16) __half g_in16 [NN * IND];
__device__ __align__(16) __half g_h16  [NN * HID];
__device__ __align__(16) __half g_f116 [NN * HID];
__device__ __align__(16) __half g_a16  [NN * HID];
__device__ __align__(16) __half g_p16  [NN * HID];   // in16 @ Wg1 (pre-spmm)
__device__ __align__(16) __half g_W1h [IND * HID];
__device__ __align__(16) __half g_W2h [HID * HID];
__device__ __align__(16) __half g_Wg1h[IND * HID];
__device__ __align__(16) __half g_Wg2h[HID * IND];

// ---------------- mma.sync helpers (HMMA m16n8k16, fp32 accum) -------------
__device__ __forceinline__ unsigned smem_u32(const void* p) {
    return (unsigned)__cvta_generic_to_shared(p);
}
__device__ __forceinline__ void ldsm4(unsigned r[4], unsigned addr) {
    asm volatile("ldmatrix.sync.aligned.m8n8.x4.shared.b16 {%0,%1,%2,%3}, [%4];"
                 : "=r"(r[0]), "=r"(r[1]), "=r"(r[2]), "=r"(r[3]) : "r"(addr));
}
__device__ __forceinline__ void ldsm4t(unsigned r[4], unsigned addr) {
    asm volatile("ldmatrix.sync.aligned.m8n8.x4.trans.shared.b16 {%0,%1,%2,%3}, [%4];"
                 : "=r"(r[0]), "=r"(r[1]), "=r"(r[2]), "=r"(r[3]) : "r"(addr));
}
__device__ __forceinline__ void mma16816(float d[4], const unsigned a[4],
                                         unsigned b0, unsigned b1) {
    asm volatile("mma.sync.aligned.m16n8k16.row.col.f32.f16.f16.f32 "
                 "{%0,%1,%2,%3}, {%4,%5,%6,%7}, {%8,%9}, {%0,%1,%2,%3};"
                 : "+f"(d[0]), "+f"(d[1]), "+f"(d[2]), "+f"(d[3])
                 : "r"(a[0]), "r"(a[1]), "r"(a[2]), "r"(a[3]), "r"(b0), "r"(b1));
}

// 64x64 output tile, 8 warps as 2(M)x4(N), each warp 32x16.
template<int LDA, int LDB>
__device__ __forceinline__ void mma_tile64(const __half* As, const __half* Bs, int K,
                                           float (&acc)[2][2][4], int lane, int warp) {
    int wm = (warp >> 2) * 32, wn = (warp & 3) * 16;
    #pragma unroll
    for (int k0 = 0; k0 < K; k0 += 16) {
        unsigned a[2][4], b[4];
        #pragma unroll
        for (int mi = 0; mi < 2; mi++) {
            unsigned ad = smem_u32(As + (wm + mi * 16 + (lane & 15)) * LDA
                                      + k0 + ((lane >> 4) << 3));
            ldsm4(a[mi], ad);
        }
        unsigned bd = smem_u32(Bs + (k0 + (lane & 15)) * LDB + wn + ((lane >> 4) << 3));
        ldsm4t(b, bd);
        #pragma unroll
        for (int mi = 0; mi < 2; mi++) {
            mma16816(acc[mi][0], a[mi], b[0], b[1]);
            mma16816(acc[mi][1], a[mi], b[2], b[3]);
        }
    }
}

// ---------------- graph prep ----------------
__global__ void k_zero_deg() {
    int i = blockIdx.x * blockDim.x + threadIdx.x;
    if (i < NN) { g_deg_in[i] = 0; g_deg_out[i] = 0; }
    if (i == 0) g_total = 0;
}

__global__ void k_deg(const int* __restrict__ src, const int* __restrict__ dst) {
    int e = blockIdx.x * blockDim.x + threadIdx.x;
    if (e < NE) {
        atomicAdd(&g_deg_in[dst[e]], 1);
        atomicAdd(&g_deg_out[src[e]], 1);
    }
}

__global__ void k_offsets() {
    int i = blockIdx.x * blockDim.x + threadIdx.x;
    if (i < NN) {
        int d = g_deg_in[i];
        int pos = atomicAdd(&g_total, d);
        g_row_beg[i] = pos;
        g_cursor[i]  = pos;
        g_din[i]  = rsqrtf((float)max(d, 1));
        g_dout[i] = rsqrtf((float)max(g_deg_out[i], 1));
    }
}

__global__ void k_scatter(const int* __restrict__ src, const int* __restrict__ dst) {
    int e = blockIdx.x * blockDim.x + threadIdx.x;
    if (e < NE) {
        int v = dst[e];
        int pos = atomicAdd(&g_cursor[v], 1);
        g_esrc[pos] = src[e];
    }
}

// ---------------- converts ----------------
__global__ void k_cvt(const float4* __restrict__ x, uint2* __restrict__ y, int n4) {
    int i = blockIdx.x * blockDim.x + threadIdx.x;
    if (i < n4) {
        float4 t = x[i];
        __half2 lo = __floats2half2_rn(t.x, t.y);
        __half2 hi = __floats2half2_rn(t.z, t.w);
        uint2 o;
        o.x = *reinterpret_cast<unsigned*>(&lo);
        o.y = *reinterpret_cast<unsigned*>(&hi);
        y[i] = o;
    }
}

__global__ void k_wcvt(const float* __restrict__ W1, const float* __restrict__ W2,
                       const float* __restrict__ Wg1, const float* __restrict__ Wg2) {
    int i = blockIdx.x * blockDim.x + threadIdx.x;
    if (i < IND * HID) g_W1h[i]  = __float2half(W1[i]);
    if (i < HID * HID) g_W2h[i]  = __float2half(W2[i]);
    if (i < IND * HID) g_Wg1h[i] = __float2half(Wg1[i]);
    if (i < HID * IND) g_Wg2h[i] = __float2half(Wg2[i]);
}

// ---------------- spmm, fp16 gather, fp32 accumulate (warp per node) -------
// mode 0: y = acc*din            (fp32 out, optional fp16 out)
// mode 1: y = base - acc*din     (Laplacian; fp32 out + optional fp16 out)
// mode 2: y16 = relu(acc*din + bias[col])   (fp16 out only; GCN conv1 tail)
__global__ void k_spmm64h(const __half2* __restrict__ x16, const float* __restrict__ gsc,
                          const float* __restrict__ base, const float* __restrict__ bias,
                          float* __restrict__ y, __half2* __restrict__ y16, int mode) {
    int w = (blockIdx.x * blockDim.x + threadIdx.x) >> 5;
    int lane = threadIdx.x & 31;
    if (w >= NN) return;
    int beg = g_row_beg[w];
    int end = beg + g_deg_in[w];
    float2 acc = make_float2(0.f, 0.f);
    #pragma unroll 4
    for (int j = beg; j < end; j++) {
        int u = g_esrc[j];
        float s = gsc[u];
        float2 t = __half22float2(x16[u * 32 + lane]);
        acc.x += t.x * s;
        acc.y += t.y * s;
    }
    float sd = g_din[w];
    float2 r;
    if (mode == 1) {
        float2 b = *reinterpret_cast<const float2*>(base + w * 64 + lane * 2);
        r.x = b.x - acc.x * sd;
        r.y = b.y - acc.y * sd;
    } else if (mode == 2) {
        r.x = fmaxf(acc.x * sd + bias[lane * 2],     0.f);
        r.y = fmaxf(acc.y * sd + bias[lane * 2 + 1], 0.f);
    } else {
        r.x = acc.x * sd;
        r.y = acc.y * sd;
    }
    if (y) *reinterpret_cast<float2*>(y + w * 64 + lane * 2) = r;
    if (y16) y16[w * 32 + lane] = __floats2half2_rn(r.x, r.y);
}

// ---------------- fused MLP + GCN pre-mult:
//   h = relu(relu(in16@W1+b1)@W2+b2);  p16 = in16@Wg1  (same A tile) -------
__global__ void __launch_bounds__(256)
k_mlp_tc(const float* __restrict__ b1, const float* __restrict__ b2,
         float* __restrict__ hf, __half* __restrict__ hh, __half* __restrict__ p16) {
    __shared__ __half sA[64 * 136];
    __shared__ __half sB[128 * 72];
    __shared__ __half sT[64 * 72];
    int tid = threadIdx.x, lane = tid & 31, warp = tid >> 5;
    int rowBase = blockIdx.x * 64;
    int wm = (warp >> 2) * 32, wn = (warp & 3) * 16;

    // A: in16 64 rows x 128
    for (int l = tid; l < 1024; l += 256) {
        int row = l >> 4, unit = l & 15;
        uint4 v = make_uint4(0, 0, 0, 0);
        int gr = rowBase + row;
        if (gr < NN) v = *reinterpret_cast<const uint4*>(g_in16 + (size_t)gr * 128 + unit * 8);
        *reinterpret_cast<uint4*>(sA + row * 136 + unit * 8) = v;
    }
    // B: W1h [128][64]
    for (int l = tid; l < 1024; l += 256) {
        int row = l >> 3, unit = l & 7;
        *reinterpret_cast<uint4*>(sB + row * 72 + unit * 8) =
            *reinterpret_cast<const uint4*>(g_W1h + (size_t)row * 64 + unit * 8);
    }
    __syncthreads();
    {
        float acc[2][2][4] = {};
        mma_tile64<136, 72>(sA, sB, 128, acc, lane, warp);
        // epilogue 1: relu+b1 -> sT (fp16)
        #pragma unroll
        for (int mi = 0; mi < 2; mi++)
        #pragma unroll
        for (int ni = 0; ni < 2; ni++)
        #pragma unroll
        for (int h = 0; h < 2; h++) {
            int rl = wm + mi * 16 + (lane >> 2) + h * 8;
            int col = wn + ni * 8 + (lane & 3) * 2;
            float v0 = fmaxf(acc[mi][ni][h * 2]     + b1[col], 0.f);
            float v1 = fmaxf(acc[mi][ni][h * 2 + 1] + b1[col + 1], 0.f);
            *reinterpret_cast<__half2*>(sT + rl * 72 + col) = __floats2half2_rn(v0, v1);
        }
    }
    __syncthreads();   // mma reads of sB(W1) done; sT complete
    // B: Wg1h [128][64]
    for (int l = tid; l < 1024; l += 256) {
        int row = l >> 3, unit = l & 7;
        *reinterpret_cast<uint4*>(sB + row * 72 + unit * 8) =
            *reinterpret_cast<const uint4*>(g_Wg1h + (size_t)row * 64 + unit * 8);
    }
    __syncthreads();
    {
        float acc[2][2][4] = {};
        mma_tile64<136, 72>(sA, sB, 128, acc, lane, warp);   // p = in16 @ Wg1
        #pragma unroll
        for (int mi = 0; mi < 2; mi++)
        #pragma unroll
        for (int ni = 0; ni < 2; ni++)
        #pragma unroll
        for (int h = 0; h < 2; h++) {
            int row = rowBase + wm + mi * 16 + (lane >> 2) + h * 8;
            if (row >= NN) continue;
            int col = wn + ni * 8 + (lane & 3) * 2;
            *reinterpret_cast<__half2*>(p16 + (size_t)row * 64 + col) =
                __floats2half2_rn(acc[mi][ni][h * 2], acc[mi][ni][h * 2 + 1]);
        }
    }
    __syncthreads();   // mma reads of sB(Wg1) done
    // B: W2h [64][64]
    for (int l = tid; l < 512; l += 256) {
        int row = l >> 3, unit = l & 7;
        *reinterpret_cast<uint4*>(sB + row * 72 + unit * 8) =
            *reinterpret_cast<const uint4*>(g_W2h + (size_t)row * 64 + unit * 8);
    }
    __syncthreads();
    {
        float acc[2][2][4] = {};
        mma_tile64<72, 72>(sT, sB, 64, acc, lane, warp);
        // epilogue 2: relu+b2 -> g_h (fp32) + g_h16
        #pragma unroll
        for (int mi = 0; mi < 2; mi++)
        #pragma unroll
        for (int ni = 0; ni < 2; ni++)
        #pragma unroll
        for (int h = 0; h < 2; h++) {
            int row = rowBase + wm + mi * 16 + (lane >> 2) + h * 8;
            if (row >= NN) continue;
            int col = wn + ni * 8 + (lane & 3) * 2;
            float v0 = fmaxf(acc[mi][ni][h * 2]     + b2[col], 0.f);
            float v1 = fmaxf(acc[mi][ni][h * 2 + 1] + b2[col + 1], 0.f);
            *reinterpret_cast<float2*>(hf + (size_t)row * 64 + col) = make_float2(v0, v1);
            *reinterpret_cast<__half2*>(hh + (size_t)row * 64 + col) = __floats2half2_rn(v0, v1);
        }
    }
}

// ---------------- fused head (TC): gather f2 = L f1 in-block, then
//  out = relu(h@Wa + f1@Wb + f2@Wc + b3) @ W4 + b4  (Wa/Wb/Wc from W3) ------
__global__ void __launch_bounds__(256)
k_head_tc(const float* __restrict__ W3, const float* __restrict__ b3,
          const float* __restrict__ W4, const float* __restrict__ b4,
          float* __restrict__ out) {
    __shared__ __half F16[64 * 72];
    __shared__ __half Ab [64 * 72];
    __shared__ __half Bc [64 * 72];
    __shared__ float  Z  [64 * 68];
    int tid = threadIdx.x, lane = tid & 31, warp = tid >> 5;
    int rowBase = blockIdx.x * 64;

    // phase 1: gather f2 rows: f2[v] = f1[v] - din[v]*sum din[u]*f116[u]
    #pragma unroll 1
    for (int i = 0; i < 8; i++) {
        int row = warp * 8 + i;
        int v = rowBase + row;
        float2 r = make_float2(0.f, 0.f);
        if (v < NN) {
            int beg = g_row_beg[v], end = beg + g_deg_in[v];
            float2 acc = make_float2(0.f, 0.f);
            #pragma unroll 4
            for (int j = beg; j < end; j++) {
                int u = g_esrc[j];
                float s = g_din[u];
                float2 t = __half22float2(*reinterpret_cast<const __half2*>(g_f116 + u * 64 + lane * 2));
                acc.x += t.x * s;
                acc.y += t.y * s;
            }
            float sd = g_din[v];
            float2 b = *reinterpret_cast<const float2*>(g_f1 + (size_t)v * 64 + lane * 2);
            r.x = b.x - acc.x * sd;
            r.y = b.y - acc.y * sd;
        }
        *reinterpret_cast<__half2*>(F16 + row * 72 + lane * 2) = __floats2half2_rn(r.x, r.y);
    }

    // phase 2: 3-source TC GEMM accumulation
    float acc[2][2][4] = {};
    for (int s3 = 0; s3 < 3; s3++) {
        if (s3 < 2) {
            const __half* src = (s3 == 0) ? g_h16 : g_f116;
            for (int l = tid; l < 512; l += 256) {
                int row = l >> 3, unit = l & 7;
                int v = rowBase + row;
                uint4 val = make_uint4(0, 0, 0, 0);
                if (v < NN) val = *reinterpret_cast<const uint4*>(src + (size_t)v * 64 + unit * 8);
                *reinterpret_cast<uint4*>(Ab + row * 72 + unit * 8) = val;
            }
        }
        for (int l = tid; l < 2048; l += 256) {
            int k = l >> 5, c = (l & 31) * 2;
            float2 w0 = *reinterpret_cast<const float2*>(W3 + (size_t)k * 64 + c);
            float2 v;
            if (s3 == 0) {
                v = make_float2(3.f * w0.x, 3.f * w0.y);
            } else if (s3 == 1) {
                float2 w1  = *reinterpret_cast<const float2*>(W3 + (size_t)(64 + k) * 64 + c);
                float2 w3v = *reinterpret_cast<const float2*>(W3 + (size_t)(192 + k) * 64 + c);
                v = make_float2(-3.f * w0.x + 3.f * w1.x + w3v.x,
                                -3.f * w0.y + 3.f * w1.y + w3v.y);
            } else {
                float2 w1  = *reinterpret_cast<const float2*>(W3 + (size_t)(64 + k) * 64 + c);
                float2 w2  = *reinterpret_cast<const float2*>(W3 + (size_t)(128 + k) * 64 + c);
                float2 w4v = *reinterpret_cast<const float2*>(W3 + (size_t)(256 + k) * 64 + c);
                v = make_float2(0.75f * w0.x - 1.5f * w1.x + 0.75f * w2.x + w4v.x,
                                0.75f * w0.y - 1.5f * w1.y + 0.75f * w2.y + w4v.y);
            }
            *reinterpret_cast<__half2*>(Bc + k * 72 + c) = __floats2half2_rn(v.x, v.y);
        }
        __syncthreads();
        mma_tile64<72, 72>((s3 == 2) ? F16 : Ab, Bc, 64, acc, lane, warp);
        __syncthreads();
    }

    // epilogue: z = relu(acc + b3) -> Z smem
    int wm = (warp >> 2) * 32, wn = (warp & 3) * 16;
    #pragma unroll
    for (int mi = 0; mi < 2; mi++)
    #pragma unroll
    for (int ni = 0; ni < 2; ni++)
    #pragma unroll
    for (int h = 0; h < 2; h++) {
        int rl = wm + mi * 16 + (lane >> 2) + h * 8;
        int col = wn + ni * 8 + (lane & 3) * 2;
        float v0 = fmaxf(acc[mi][ni][h * 2]     + b3[col], 0.f);
        float v1 = fmaxf(acc[mi][ni][h * 2 + 1] + b3[col + 1], 0.f);
        Z[rl * 68 + col]     = v0;
        Z[rl * 68 + col + 1] = v1;
    }
    __syncthreads();

    // 64 -> 2 contraction with W4
    int rl = warp * 8 + (lane >> 2);
    int c0 = (lane & 3) * 16;
    float p0 = 0.f, p1 = 0.f;
    #pragma unroll
    for (int c = 0; c < 16; c++) {
        float z = Z[rl * 68 + c0 + c];
        p0 += z * W4[(c0 + c) * 2];
        p1 += z * W4[(c0 + c) * 2 + 1];
    }
    p0 += __shfl_down_sync(0xffffffffu, p0, 2, 4);
    p0 += __shfl_down_sync(0xffffffffu, p0, 1, 4);
    p1 += __shfl_down_sync(0xffffffffu, p1, 2, 4);
    p1 += __shfl_down_sync(0xffffffffu, p1, 1, 4);
    int row = rowBase + rl;
    if ((lane & 3) == 0 && row < NN) {
        out[row * 2]     = p0 + b4[0];
        out[row * 2 + 1] = p1 + b4[1];
    }
}

// ---------------- fused GCN tail (TC): gather din*sum(dout*a16) in-block,
//   then emb = A @ Wg2 + bg2 (N=128 via two 64-col passes) ------------------
__global__ void __launch_bounds__(256)
k_gcn2_tc(const float* __restrict__ bg2, float* __restrict__ emb) {
    __shared__ __half Ab[64 * 72];
    __shared__ __half Bw[64 * 136];
    int tid = threadIdx.x, lane = tid & 31, warp = tid >> 5;
    int rowBase = blockIdx.x * 64;

    // phase 1: gather
    #pragma unroll 1
    for (int i = 0; i < 8; i++) {
        int row = warp * 8 + i;
        int v = rowBase + row;
        float2 r = make_float2(0.f, 0.f);
        if (v < NN) {
            int beg = g_row_beg[v], end = beg + g_deg_in[v];
            float2 acc = make_float2(0.f, 0.f);
            #pragma unroll 4
            for (int j = beg; j < end; j++) {
                int u = g_esrc[j];
                float s = g_dout[u];
                float2 t = __half22float2(*reinterpret_cast<const __half2*>(g_a16 + u * 64 + lane * 2));
                acc.x += t.x * s;
                acc.y += t.y * s;
            }
            float sd = g_din[v];
            r.x = acc.x * sd;
            r.y = acc.y * sd;
        }
        *reinterpret_cast<__half2*>(Ab + row * 72 + lane * 2) = __floats2half2_rn(r.x, r.y);
    }
    // B: Wg2h [64][128]
    for (int l = tid; l < 1024; l += 256) {
        int row = l >> 4, unit = l & 15;
        *reinterpret_cast<uint4*>(Bw + row * 136 + unit * 8) =
            *reinterpret_cast<const uint4*>(g_Wg2h + (size_t)row * 128 + unit * 8);
    }
    __syncthreads();

    int wm = (warp >> 2) * 32, wn = (warp & 3) * 16;
    #pragma unroll 1
    for (int cb = 0; cb < 128; cb += 64) {
        float acc[2][2][4] = {};
        mma_tile64<72, 136>(Ab, Bw + cb, 64, acc, lane, warp);
        #pragma unroll
        for (int mi = 0; mi < 2; mi++)
        #pragma unroll
        for (int ni = 0; ni < 2; ni++)
        #pragma unroll
        for (int h = 0; h < 2; h++) {
            int row = rowBase + wm + mi * 16 + (lane >> 2) + h * 8;
            if (row >= NN) continue;
            int col = cb + wn + ni * 8 + (lane & 3) * 2;
            float v0 = acc[mi][ni][h * 2]     + bg2[col];
            float v1 = acc[mi][ni][h * 2 + 1] + bg2[col + 1];
            *reinterpret_cast<float2*>(emb + (size_t)row * 128 + col) = make_float2(v0, v1);
        }
    }
}

// ---------------- launch (two forked streams inside capture) ---------------
extern "C" void kernel_launch(void* const* d_in, const int* in_sizes, int n_in,
                              void* d_out, int out_size) {
    const float* in_feat = (const float*)d_in[0];
    const int*   src     = (const int*)d_in[1];
    const int*   dst     = (const int*)d_in[2];
    const float* W1 = (const float*)d_in[3];
    const float* b1 = (const float*)d_in[4];
    const float* W2 = (const float*)d_in[5];
    const float* b2 = (const float*)d_in[6];
    const float* W3 = (const float*)d_in[7];
    const float* b3 = (const float*)d_in[8];
    const float* W4 = (const float*)d_in[9];
    const float* b4 = (const float*)d_in[10];
    const float* Wg1 = (const float*)d_in[11];
    const float* bg1 = (const float*)d_in[12];
    const float* Wg2 = (const float*)d_in[13];
    const float* bg2 = (const float*)d_in[14];

    float* out = (float*)d_out;          // [NN,2]
    float* emb = out + NN * 2;           // [NN,128]

    float  *p_h, *p_f1, *p_din, *p_dout;
    __half *p_in16, *p_h16, *p_f116, *p_a16, *p_p16;
    cudaGetSymbolAddress((void**)&p_h,    g_h);
    cudaGetSymbolAddress((void**)&p_f1,   g_f1);
    cudaGetSymbolAddress((void**)&p_din,  g_din);
    cudaGetSymbolAddress((void**)&p_dout, g_dout);
    cudaGetSymbolAddress((void**)&p_in16, g_in16);
    cudaGetSymbolAddress((void**)&p_h16,  g_h16);
    cudaGetSymbolAddress((void**)&p_f116, g_f116);
    cudaGetSymbolAddress((void**)&p_a16,  g_a16);
    cudaGetSymbolAddress((void**)&p_p16,  g_p16);

    // streams/events created once on the uncaptured correctness call; reused
    // during capture (creation during capture is illegal). Same work per call.
    static cudaStream_t s1 = nullptr, s2 = nullptr;
    static cudaEvent_t evRoot, evGraph, evMlp, evS1, evS2;
    if (!s1) {
        cudaStreamCreateWithFlags(&s1, cudaStreamNonBlocking);
        cudaStreamCreateWithFlags(&s2, cudaStreamNonBlocking);
        cudaEventCreateWithFlags(&evRoot,  cudaEventDisableTiming);
        cudaEventCreateWithFlags(&evGraph, cudaEventDisableTiming);
        cudaEventCreateWithFlags(&evMlp,   cudaEventDisableTiming);
        cudaEventCreateWithFlags(&evS1,    cudaEventDisableTiming);
        cudaEventCreateWithFlags(&evS2,    cudaEventDisableTiming);
    }

    const int TB = 256;
    int nBlkN = (NN + TB - 1) / TB;
    int nBlkE = (NE + TB - 1) / TB;
    int spmmBlocks = (NN * 32 + TB - 1) / TB;
    int tileBlocks = (NN + 63) / 64;

    // ---- fork ----
    cudaEventRecord(evRoot, 0);
    cudaStreamWaitEvent(s1, evRoot, 0);
    cudaStreamWaitEvent(s2, evRoot, 0);

    // Submission order keeps the fused MLP at launch slot #4 for ncu.
    k_zero_deg<<<nBlkN, TB>>>();                                              // 1
    k_cvt<<<(NN * 32 + TB - 1) / TB, TB, 0, s1>>>((const float4*)in_feat,
                                                  (uint2*)p_in16, NN * 32);   // 2
    k_wcvt<<<(IND * HID + TB - 1) / TB, TB, 0, s1>>>(W1, W2, Wg1, Wg2);       // 3
    k_mlp_tc<<<tileBlocks, 256, 0, s1>>>(b1, b2, p_h, p_h16, p_p16);          // 4 (profiled)
    cudaEventRecord(evMlp, s1);
    k_deg<<<nBlkE, TB>>>(src, dst);                                           // 5
    k_offsets<<<nBlkN, TB>>>();                                               // 6
    k_scatter<<<nBlkE, TB>>>(src, dst);                                       // 7
    cudaEventRecord(evGraph, 0);

    // ---- s1: band branch (needs graph) ----
    cudaStreamWaitEvent(s1, evGraph, 0);
    k_spmm64h<<<spmmBlocks, TB, 0, s1>>>((const __half2*)p_h16, p_din, p_h,
                                         nullptr, p_f1, (__half2*)p_f116, 1); // 8
    k_head_tc<<<tileBlocks, 256, 0, s1>>>(W3, b3, W4, b4, out);               // 9
    cudaEventRecord(evS1, s1);

    // ---- s2: GCN branch (needs graph + p16) ----
    cudaStreamWaitEvent(s2, evGraph, 0);
    cudaStreamWaitEvent(s2, evMlp, 0);
    k_spmm64h<<<spmmBlocks, TB, 0, s2>>>((const __half2*)p_p16, p_dout, nullptr,
                                         bg1, nullptr, (__half2*)p_a16, 2);   // 10
    k_gcn2_tc<<<tileBlocks, 256, 0, s2>>>(bg2, emb);                          // 11
    cudaEventRecord(evS2, s2);

    // ---- join ----
    cudaStreamWaitEvent(0, evS1, 0);
    cudaStreamWaitEvent(0, evS2, 0);
}